// round 4
// baseline (speedup 1.0000x reference)
#include <cuda_runtime.h>
#include <cuda_bf16.h>
#include <math.h>

// Problem constants (fixed inputs)
#define BB 2
#define SS 2048
#define DD 768
#define HH 12
#define DH 64
#define WW 128
#define NC (SS / WW)      // 16
#define LL 4
#define FFD 3072
#define NTOK (BB * SS)    // 4096
#define BKK 16

// ---------------- scratch (device globals; no allocation allowed) ----------
__device__ float g_h [NTOK * DD];
__device__ float g_q [NTOK * DD];
__device__ float g_k [NTOK * DD];
__device__ float g_v [NTOK * DD];
__device__ float g_kg[NTOK * DD];
__device__ float g_vg[NTOK * DD];
__device__ float g_a [NTOK * DD];
__device__ float g_t [NTOK * DD];
__device__ float g_ff[NTOK * FFD];
__device__ float g_qg[BB * DD];

// ---------------- GEMM core: C = (A[.,K] @ B[K,N] + bias) * scale, opt GELU -
// 128x128 tile, BK=16, 256 threads, 8x8 microtile, double-buffered smem.
__device__ __forceinline__ void gemm_core(
    const float* __restrict__ A, const float* __restrict__ B,
    const float* __restrict__ bias, float* __restrict__ C,
    int N, int K, int ep, float scale, int brow, int bcol,
    float (*As)[BKK][128], float (*Bs)[BKK][128])
{
    const int tid = threadIdx.x;
    const int tr = tid >> 4;        // 0..15
    const int tc = tid & 15;        // 0..15
    const int ntiles = K / BKK;

    float4 ra[2], rb[2];

    // prologue: tile 0 -> smem[0]
#pragma unroll
    for (int i = 0; i < 2; i++) {
        int f4 = tid + i * 256;
        int row = f4 >> 2, kc = (f4 & 3) * 4;
        ra[i] = *(const float4*)&A[(size_t)(brow + row) * K + kc];
        int krow = f4 >> 5, nc = (f4 & 31) * 4;
        rb[i] = *(const float4*)&B[(size_t)krow * N + bcol + nc];
    }
#pragma unroll
    for (int i = 0; i < 2; i++) {
        int f4 = tid + i * 256;
        int row = f4 >> 2, kc = (f4 & 3) * 4;
        As[0][kc + 0][row] = ra[i].x;
        As[0][kc + 1][row] = ra[i].y;
        As[0][kc + 2][row] = ra[i].z;
        As[0][kc + 3][row] = ra[i].w;
        int krow = f4 >> 5, nc = (f4 & 31) * 4;
        *(float4*)&Bs[0][krow][nc] = rb[i];
    }
    __syncthreads();

    float acc[8][8];
#pragma unroll
    for (int i = 0; i < 8; i++)
#pragma unroll
        for (int j = 0; j < 8; j++) acc[i][j] = 0.f;

    int buf = 0;
    for (int t = 0; t < ntiles; t++) {
        if (t + 1 < ntiles) {
            const int k0 = (t + 1) * BKK;
#pragma unroll
            for (int i = 0; i < 2; i++) {
                int f4 = tid + i * 256;
                int row = f4 >> 2, kc = (f4 & 3) * 4;
                ra[i] = *(const float4*)&A[(size_t)(brow + row) * K + k0 + kc];
                int krow = f4 >> 5, nc = (f4 & 31) * 4;
                rb[i] = *(const float4*)&B[(size_t)(k0 + krow) * N + bcol + nc];
            }
        }
#pragma unroll
        for (int kk = 0; kk < BKK; kk++) {
            float ar[8], br[8];
            *(float4*)&ar[0] = *(const float4*)&As[buf][kk][tr * 8 + 0];
            *(float4*)&ar[4] = *(const float4*)&As[buf][kk][tr * 8 + 4];
            *(float4*)&br[0] = *(const float4*)&Bs[buf][kk][tc * 8 + 0];
            *(float4*)&br[4] = *(const float4*)&Bs[buf][kk][tc * 8 + 4];
#pragma unroll
            for (int i = 0; i < 8; i++)
#pragma unroll
                for (int j = 0; j < 8; j++) acc[i][j] += ar[i] * br[j];
        }
        if (t + 1 < ntiles) {
            const int nb = buf ^ 1;
#pragma unroll
            for (int i = 0; i < 2; i++) {
                int f4 = tid + i * 256;
                int row = f4 >> 2, kc = (f4 & 3) * 4;
                As[nb][kc + 0][row] = ra[i].x;
                As[nb][kc + 1][row] = ra[i].y;
                As[nb][kc + 2][row] = ra[i].z;
                As[nb][kc + 3][row] = ra[i].w;
                int krow = f4 >> 5, nc = (f4 & 31) * 4;
                *(float4*)&Bs[nb][krow][nc] = rb[i];
            }
            __syncthreads();
            buf = nb;
        }
    }

#pragma unroll
    for (int i = 0; i < 8; i++) {
        int r = brow + tr * 8 + i;
#pragma unroll
        for (int j = 0; j < 8; j++) {
            int cidx = bcol + tc * 8 + j;
            float vv = (acc[i][j] + bias[cidx]) * scale;
            if (ep == 1) vv = 0.5f * vv * (1.f + erff(vv * 0.70710678118654752f));
            C[(size_t)r * N + cidx] = vv;
        }
    }
}

// plain single-GEMM kernel
__global__ __launch_bounds__(256, 2) void sgemm_kernel(
    const float* __restrict__ A, const float* __restrict__ B,
    const float* __restrict__ bias, float* __restrict__ C,
    int N, int K, int ep, float scale)
{
    __shared__ float As[2][BKK][128];
    __shared__ float Bs[2][BKK][128];
    gemm_core(A, B, bias, C, N, K, ep, scale,
              blockIdx.y * 128, blockIdx.x * 128, As, Bs);
}

// batched 5-projection GEMM: all segments share A; N=768 each.
struct Proj5 {
    const float* B[5];
    const float* bias[5];
    float* C[5];
};
__global__ __launch_bounds__(256, 2) void sgemm_proj5_kernel(
    const float* __restrict__ A, Proj5 p, int K)
{
    __shared__ float As[2][BKK][128];
    __shared__ float Bs[2][BKK][128];
    const int seg  = blockIdx.x / 6;                 // 0..4
    const int bcol = (blockIdx.x % 6) * 128;
    const float scale = (seg == 0) ? 0.125f : 1.f;   // q projection scaled
    gemm_core(A, p.B[seg], p.bias[seg], p.C[seg], DD, K, 0, scale,
              blockIdx.y * 128, bcol, As, Bs);
}

// ---------------- embedding gather ------------------------------------------
__global__ void embed_kernel(const int* __restrict__ src,
                             const float* __restrict__ tok,
                             const float* __restrict__ pos,
                             float* __restrict__ out)
{
    int row = blockIdx.x;           // b*S + s
    int s = row % SS;
    int t = src[row];
    for (int i = threadIdx.x; i < DD; i += blockDim.x)
        out[(size_t)row * DD + i] = tok[(size_t)t * DD + i] + pos[(size_t)s * DD + i];
}

// ---------------- add + layernorm (row = token, 256 threads, D=768) ---------
__global__ __launch_bounds__(256) void add_ln_kernel(
    const float* __restrict__ x, const float* __restrict__ res,
    const float* __restrict__ gam, const float* __restrict__ bet,
    float* __restrict__ out)
{
    int row = blockIdx.x;
    int tid = threadIdx.x;
    const float* xr = x + (size_t)row * DD;
    const float* rr = res ? res + (size_t)row * DD : nullptr;
    float v[3];
    float lsum = 0.f, lsq = 0.f;
#pragma unroll
    for (int i = 0; i < 3; i++) {
        int idx = tid + i * 256;
        float t = xr[idx];
        if (rr) t += rr[idx];
        v[i] = t; lsum += t; lsq += t * t;
    }
    __shared__ float r1[256], r2[256];
    r1[tid] = lsum; r2[tid] = lsq;
    __syncthreads();
    for (int o = 128; o > 0; o >>= 1) {
        if (tid < o) { r1[tid] += r1[tid + o]; r2[tid] += r2[tid + o]; }
        __syncthreads();
    }
    float mean = r1[0] * (1.f / DD);
    float var  = r2[0] * (1.f / DD) - mean * mean;
    float inv  = rsqrtf(var + 1e-5f);
#pragma unroll
    for (int i = 0; i < 3; i++) {
        int idx = tid + i * 256;
        out[(size_t)row * DD + idx] = (v[i] - mean) * inv * gam[idx] + bet[idx];
    }
}

// ---------------- qg = (h[:,0] @ Wqg + bqg) / 8 ------------------------------
__global__ void qg_kernel(const float* __restrict__ h,
                          const float* __restrict__ W,
                          const float* __restrict__ b,
                          float* __restrict__ qg)
{
    int bb = blockIdx.x;
    int n  = threadIdx.x;   // 0..767
    const float* hr = h + (size_t)bb * SS * DD;
    float acc = b[n];
    for (int k = 0; k < DD; k++) acc += hr[k] * W[(size_t)k * DD + n];
    qg[bb * DD + n] = acc * 0.125f;
}

// ---------------- sliding-window + global-slot attention ---------------------
// grid (NC, H, B), block 128 (one thread per query in chunk)
__global__ __launch_bounds__(128) void sliding_attn_kernel(
    const float* __restrict__ q, const float* __restrict__ k,
    const float* __restrict__ v, const int* __restrict__ mask,
    float* __restrict__ outp)
{
    extern __shared__ float sm[];
    float* ks = sm;                    // 128 x 64
    float* vs = sm + 128 * 64;         // 128 x 64

    const int c = blockIdx.x, hh = blockIdx.y, b = blockIdx.z;
    const int qi = threadIdx.x;
    const int t  = c * WW + qi;
    const size_t base = (size_t)(b * SS) * DD + hh * DH;

    // q row in registers
    float qr[DH];
#pragma unroll
    for (int d = 0; d < DH; d++)
        qr[d] = q[base + (size_t)t * DD + d];

    float m, l, acc[DH];
    // global key slot (k,v at s=0)
    {
        float sc;
        if (mask[b * SS + 0] != 0) {
            sc = 0.f;
#pragma unroll
            for (int d = 0; d < DH; d++)
                sc += qr[d] * k[base + d];
        } else sc = -1e9f;
        m = sc; l = 1.f;
#pragma unroll
        for (int d = 0; d < DH; d++) acc[d] = v[base + d];
    }

    for (int tile = 0; tile < 3; tile++) {
        int s0 = c * WW - WW + tile * WW;
        __syncthreads();
        // cooperative k/v tile load (zero-fill out-of-range)
        for (int li = qi; li < 128 * 64; li += 128) {
            int j = li >> 6, d = li & 63;
            int srow = s0 + j;
            float kv = 0.f, vv = 0.f;
            if (srow >= 0 && srow < SS) {
                kv = k[base + (size_t)srow * DD + d];
                vv = v[base + (size_t)srow * DD + d];
            }
            ks[j * 64 + d] = kv;
            vs[j * 64 + d] = vv;
        }
        __syncthreads();

        for (int j = 0; j < 128; j++) {
            int jj = tile * 128 + j;
            if (jj < qi || jj > qi + 2 * WW) continue;   // rel window
            int srow = s0 + j;
            if (srow < 0 || srow >= SS) continue;
            if (mask[b * SS + srow] == 0) continue;
            float sc = 0.f;
#pragma unroll
            for (int d = 0; d < DH; d++)
                sc += qr[d] * ks[j * 64 + d];
            if (sc > m) {
                float f = expf(m - sc);
                l *= f;
#pragma unroll
                for (int d = 0; d < DH; d++) acc[d] *= f;
                m = sc;
            }
            float w = expf(sc - m);
            l += w;
#pragma unroll
            for (int d = 0; d < DH; d++) acc[d] += w * vs[j * 64 + d];
        }
    }

    float invl = 1.f / l;
#pragma unroll
    for (int d = 0; d < DH; d++)
        outp[base + (size_t)t * DD + d] = acc[d] * invl;
}

// ---------------- global attention for token 0 -------------------------------
// grid (H, B), block 256
__global__ __launch_bounds__(256) void global_attn_kernel(
    const float* __restrict__ qg, const float* __restrict__ kg,
    const float* __restrict__ vg, const int* __restrict__ mask,
    float* __restrict__ outp)
{
    __shared__ float sc[SS];
    __shared__ float red[256];
    const int hh = blockIdx.x, b = blockIdx.y;
    const int tid = threadIdx.x;
    const size_t base = (size_t)(b * SS) * DD + hh * DH;

    float qr[DH];
#pragma unroll
    for (int d = 0; d < DH; d++) qr[d] = qg[b * DD + hh * DH + d];

    for (int s = tid; s < SS; s += 256) {
        float d0;
        if (mask[b * SS + s] != 0) {
            d0 = 0.f;
#pragma unroll
            for (int d = 0; d < DH; d++)
                d0 += qr[d] * kg[base + (size_t)s * DD + d];
        } else d0 = -1e9f;
        sc[s] = d0;
    }
    __syncthreads();

    // max
    float mx = -1e30f;
    for (int s = tid; s < SS; s += 256) mx = fmaxf(mx, sc[s]);
    red[tid] = mx; __syncthreads();
    for (int o = 128; o > 0; o >>= 1) {
        if (tid < o) red[tid] = fmaxf(red[tid], red[tid + o]);
        __syncthreads();
    }
    mx = red[0];
    __syncthreads();

    // exp + sum
    float ps = 0.f;
    for (int s = tid; s < SS; s += 256) {
        float e = expf(sc[s] - mx);
        sc[s] = e; ps += e;
    }
    red[tid] = ps; __syncthreads();
    for (int o = 128; o > 0; o >>= 1) {
        if (tid < o) red[tid] += red[tid + o];
        __syncthreads();
    }
    float total = red[0];
    __syncthreads();

    // weighted sum of vg: thread = (d = tid&63, group = tid>>6)
    int d = tid & 63, g = tid >> 6;
    float a = 0.f;
    for (int s = g; s < SS; s += 4)
        a += sc[s] * vg[base + (size_t)s * DD + d];
    red[tid] = a; __syncthreads();
    if (g == 0) {
        a = red[tid] + red[tid + 64] + red[tid + 128] + red[tid + 192];
        outp[base + d] = a / total;     // overwrite token-0 attention output
    }
}

// ---------------- classifier head -------------------------------------------
__global__ void cls_kernel(const float* __restrict__ h,
                           const float* __restrict__ Wc,
                           const float* __restrict__ bc,
                           const int* __restrict__ mask,
                           float* __restrict__ out)
{
    int tid = threadIdx.x;
    if (tid < BB * 3) {
        int b = tid / 3, j = tid % 3;
        const float* hr = h + (size_t)b * SS * DD;
        float acc = bc[j];
        for (int kx = 0; kx < DD; kx++) acc += hr[kx] * Wc[kx * 3 + j];
        float sg = 1.f / (1.f + expf(-acc));
        out[j * BB + b] = sg;                       // verdict | pros | cons
        if (j == 0) out[3 * BB + b] = (float)mask[b * SS + 0];  // example_masks
    }
}

// ---------------- host orchestration -----------------------------------------
static inline void run_sgemm(const float* A, const float* B, const float* bias,
                             float* C, int M, int N, int K, int ep, float scale)
{
    dim3 grid(N / 128, M / 128);
    sgemm_kernel<<<grid, 256>>>(A, B, bias, C, N, K, ep, scale);
}

extern "C" void kernel_launch(void* const* d_in, const int* in_sizes, int n_in,
                              void* d_out, int out_size)
{
    const int*   src      = (const int*)  d_in[0];
    const int*   mask_src = (const int*)  d_in[1];
    const float* emb_tok  = (const float*)d_in[3];
    const float* emb_pos  = (const float*)d_in[4];
    const float* emb_ln_s = (const float*)d_in[5];
    const float* emb_ln_b = (const float*)d_in[6];
    const float* Wq  = (const float*)d_in[7];
    const float* bq  = (const float*)d_in[8];
    const float* Wk  = (const float*)d_in[9];
    const float* bk  = (const float*)d_in[10];
    const float* Wv  = (const float*)d_in[11];
    const float* bv  = (const float*)d_in[12];
    const float* Wo  = (const float*)d_in[13];
    const float* bo  = (const float*)d_in[14];
    const float* Wqg = (const float*)d_in[15];
    const float* bqg = (const float*)d_in[16];
    const float* Wkg = (const float*)d_in[17];
    const float* bkg = (const float*)d_in[18];
    const float* Wvg = (const float*)d_in[19];
    const float* bvg = (const float*)d_in[20];
    const float* ln1_s = (const float*)d_in[21];
    const float* ln1_b = (const float*)d_in[22];
    const float* W1  = (const float*)d_in[23];
    const float* b1  = (const float*)d_in[24];
    const float* W2  = (const float*)d_in[25];
    const float* b2  = (const float*)d_in[26];
    const float* ln2_s = (const float*)d_in[27];
    const float* ln2_b = (const float*)d_in[28];
    const float* Wcls = (const float*)d_in[29];
    const float* bcls = (const float*)d_in[30];
    float* out = (float*)d_out;

    float *p_h, *p_q, *p_k, *p_v, *p_kg, *p_vg, *p_a, *p_t, *p_ff, *p_qg;
    cudaGetSymbolAddress((void**)&p_h,  g_h);
    cudaGetSymbolAddress((void**)&p_q,  g_q);
    cudaGetSymbolAddress((void**)&p_k,  g_k);
    cudaGetSymbolAddress((void**)&p_v,  g_v);
    cudaGetSymbolAddress((void**)&p_kg, g_kg);
    cudaGetSymbolAddress((void**)&p_vg, g_vg);
    cudaGetSymbolAddress((void**)&p_a,  g_a);
    cudaGetSymbolAddress((void**)&p_t,  g_t);
    cudaGetSymbolAddress((void**)&p_ff, g_ff);
    cudaGetSymbolAddress((void**)&p_qg, g_qg);

    // opt-in to >48KB dynamic smem for sliding attention (64 KB)
    static const size_t SLIDE_SMEM = (2 * 128 * 64) * sizeof(float);
    cudaFuncSetAttribute(sliding_attn_kernel,
                         cudaFuncAttributeMaxDynamicSharedMemorySize,
                         (int)SLIDE_SMEM);

    // embedding + LN
    embed_kernel<<<NTOK, 256>>>(src, emb_tok, emb_pos, p_t);
    add_ln_kernel<<<NTOK, 256>>>(p_t, nullptr, emb_ln_s, emb_ln_b, p_h);

    for (int l = 0; l < LL; l++) {
        const size_t wo = (size_t)l * DD * DD;
        const size_t bo_ = (size_t)l * DD;

        // batched projections (q scaled by 0.125 inside kernel, seg 0)
        Proj5 p;
        p.B[0] = Wq + wo;  p.bias[0] = bq + bo_;  p.C[0] = p_q;
        p.B[1] = Wk + wo;  p.bias[1] = bk + bo_;  p.C[1] = p_k;
        p.B[2] = Wv + wo;  p.bias[2] = bv + bo_;  p.C[2] = p_v;
        p.B[3] = Wkg + wo; p.bias[3] = bkg + bo_; p.C[3] = p_kg;
        p.B[4] = Wvg + wo; p.bias[4] = bvg + bo_; p.C[4] = p_vg;
        sgemm_proj5_kernel<<<dim3(30, NTOK / 128), 256>>>(p_h, p, DD);
        qg_kernel<<<BB, DD>>>(p_h, Wqg + wo, bqg + bo_, p_qg);

        // attention
        sliding_attn_kernel<<<dim3(NC, HH, BB), 128, SLIDE_SMEM>>>(
            p_q, p_k, p_v, mask_src, p_a);
        global_attn_kernel<<<dim3(HH, BB), 256>>>(
            p_qg, p_kg, p_vg, mask_src, p_a);

        // output proj + residual LN
        run_sgemm(p_a, Wo + wo, bo + bo_, p_t, NTOK, DD, DD, 0, 1.f);
        add_ln_kernel<<<NTOK, 256>>>(p_t, p_h, ln1_s + bo_, ln1_b + bo_, p_h);

        // FFN
        run_sgemm(p_h, W1 + (size_t)l * DD * FFD, b1 + (size_t)l * FFD,
                  p_ff, NTOK, FFD, DD, 1, 1.f);
        run_sgemm(p_ff, W2 + (size_t)l * FFD * DD, b2 + bo_,
                  p_t, NTOK, DD, FFD, 0, 1.f);
        add_ln_kernel<<<NTOK, 256>>>(p_t, p_h, ln2_s + bo_, ln2_b + bo_, p_h);
    }

    cls_kernel<<<1, 32>>>(p_h, Wcls, bcls, mask_src, out);
}

// round 12
// speedup vs baseline: 1.7330x; 1.7330x over previous
#include <cuda_runtime.h>
#include <cuda_bf16.h>
#include <math.h>
#include <stdint.h>

// Problem constants (fixed inputs)
#define BB 2
#define SS 2048
#define DD 768
#define HH 12
#define DH 64
#define WW 128
#define NC (SS / WW)      // 16
#define LL 4
#define FFD 3072
#define NTOK (BB * SS)    // 4096

// ---------------- scratch (device globals; no allocation allowed) ----------
__device__ float g_h [NTOK * DD];
__device__ float g_q [NTOK * DD];
__device__ float g_k [NTOK * DD];
__device__ float g_v [NTOK * DD];
__device__ float g_kg[NTOK * DD];
__device__ float g_vg[NTOK * DD];
__device__ float g_a [NTOK * DD];
__device__ float g_t [NTOK * DD];
__device__ float g_ff[NTOK * FFD];
__device__ float g_qg[BB * DD];

// transposed/split bf16 weights: per layer 6x(768x768) + w1(3072x768) + w2(768x3072)
#define WT_MAT   (DD * DD)
#define WT_LAYER (6 * WT_MAT + 2 * DD * FFD)
__device__ __nv_bfloat16 g_wt_h[LL * WT_LAYER];
__device__ __nv_bfloat16 g_wt_l[LL * WT_LAYER];

// ================= helpers ==================================================
__device__ __forceinline__ uint32_t smem_u32(const void* p) {
    uint32_t a;
    asm("{ .reg .u64 t; cvta.to.shared.u64 t, %1; cvt.u32.u64 %0, t; }"
        : "=r"(a) : "l"(p));
    return a;
}
__device__ __forceinline__ void ldsm_x4(uint32_t* r, uint32_t addr) {
    asm volatile("ldmatrix.sync.aligned.m8n8.x4.shared.b16 {%0,%1,%2,%3}, [%4];"
                 : "=r"(r[0]), "=r"(r[1]), "=r"(r[2]), "=r"(r[3]) : "r"(addr));
}
__device__ __forceinline__ void mma16816(float* d, const uint32_t* a,
                                         const uint32_t* b) {
    asm volatile("mma.sync.aligned.m16n8k16.row.col.f32.bf16.bf16.f32 "
                 "{%0,%1,%2,%3}, {%4,%5,%6,%7}, {%8,%9}, {%0,%1,%2,%3};"
                 : "+f"(d[0]), "+f"(d[1]), "+f"(d[2]), "+f"(d[3])
                 : "r"(a[0]), "r"(a[1]), "r"(a[2]), "r"(a[3]),
                   "r"(b[0]), "r"(b[1]));
}

// ================= mma.sync GEMM ===========================================
// C[M,N] = (A[M,K] @ W[K,N] + bias) * scale (+gelu).  W pre-transposed and
// hi/lo split as Bt[N,K] bf16.  CTA tile 128x128, 8 warps (4m x 2n),
// warp tile 32x64, K-chunk 32.  3-term bf16 split: hi*hi + lo*hi + hi*lo.
// smem rows padded to 80B (chunk row = 64B data + 16B pad) -> ldmatrix
// conflict-free (80*i mod 128 covers 8 disjoint 16B bank groups).
#define SM_AH 0
#define SM_AL 10240
#define SM_BH 20480
#define SM_BL 30720
#define SM_TOT 40960

__device__ __forceinline__ void gemm_mma_core(
    const float* __restrict__ A,
    const __nv_bfloat16* __restrict__ Bh, const __nv_bfloat16* __restrict__ Bl,
    const float* __restrict__ bias, float* __restrict__ C,
    int N, int K, int ep, float scale, int brow, int bcol)
{
    __shared__ __align__(16) char sm[SM_TOT];
    const uint32_t smb = smem_u32(sm);
    const int tid  = threadIdx.x;
    const int lane = tid & 31, wrp = tid >> 5;
    const int wm = wrp >> 1, wn = wrp & 1;       // 4x2 warp grid

    float acc[2][8][4];
#pragma unroll
    for (int mt = 0; mt < 2; mt++)
#pragma unroll
        for (int nt = 0; nt < 8; nt++)
#pragma unroll
            for (int j = 0; j < 4; j++) acc[mt][nt][j] = 0.f;

    const int nch = K >> 5;
    for (int ch = 0; ch < nch; ch++) {
        const int k0 = ch << 5;
        __syncthreads();
        // ---- stage A: 128 rows x 32 k fp32 -> bf16 hi/lo -------------------
#pragma unroll
        for (int i = 0; i < 4; i++) {
            int f4 = tid + i * 256;
            int row = f4 >> 3, c4 = (f4 & 7) << 2;
            float4 v = *(const float4*)&A[(size_t)(brow + row) * K + k0 + c4];
            float rx = v.x - __bfloat162float(__float2bfloat16_rn(v.x));
            float ry = v.y - __bfloat162float(__float2bfloat16_rn(v.y));
            float rz = v.z - __bfloat162float(__float2bfloat16_rn(v.z));
            float rw = v.w - __bfloat162float(__float2bfloat16_rn(v.w));
            __nv_bfloat162 h01 = __floats2bfloat162_rn(v.x, v.y);
            __nv_bfloat162 h23 = __floats2bfloat162_rn(v.z, v.w);
            __nv_bfloat162 l01 = __floats2bfloat162_rn(rx, ry);
            __nv_bfloat162 l23 = __floats2bfloat162_rn(rz, rw);
            uint32_t off = row * 80 + c4 * 2;
            *(uint2*)(sm + SM_AH + off) =
                make_uint2(*(uint32_t*)&h01, *(uint32_t*)&h23);
            *(uint2*)(sm + SM_AL + off) =
                make_uint2(*(uint32_t*)&l01, *(uint32_t*)&l23);
        }
        // ---- stage B: 128 n-rows x 32 k bf16 (already [N,K]) ---------------
#pragma unroll
        for (int i = 0; i < 2; i++) {
            int idx = tid + i * 256;
            int row = idx >> 2, seg = idx & 3;
            uint32_t off = row * 80 + seg * 16;
            *(uint4*)(sm + SM_BH + off) =
                *(const uint4*)&Bh[(size_t)(bcol + row) * K + k0 + seg * 8];
            *(uint4*)(sm + SM_BL + off) =
                *(const uint4*)&Bl[(size_t)(bcol + row) * K + k0 + seg * 8];
        }
        __syncthreads();

#pragma unroll
        for (int ks = 0; ks < 2; ks++) {
            const uint32_t kb = ks * 32 + ((lane >> 3) & 1) * 16;  // B k-byte
            const uint32_t ka = ks * 32 + (lane >> 4) * 16;        // A k-byte
            uint32_t ah[2][4], aw[2][4], bb[8][2];
            // A-hi fragments
#pragma unroll
            for (int mt = 0; mt < 2; mt++) {
                uint32_t r = wm * 32 + mt * 16 + (lane & 15);
                ldsm_x4(ah[mt], smb + SM_AH + r * 80 + ka);
            }
            // B-hi fragments (pairs of n8 tiles)
#pragma unroll
            for (int p = 0; p < 4; p++) {
                uint32_t r = wn * 64 + p * 16 + ((lane >> 4) & 1) * 8 + (lane & 7);
                uint32_t t4[4];
                ldsm_x4(t4, smb + SM_BH + r * 80 + kb);
                bb[2 * p][0] = t4[0]; bb[2 * p][1] = t4[1];
                bb[2 * p + 1][0] = t4[2]; bb[2 * p + 1][1] = t4[3];
            }
            // term 1: ah * bh
#pragma unroll
            for (int mt = 0; mt < 2; mt++)
#pragma unroll
                for (int nt = 0; nt < 8; nt++)
                    mma16816(acc[mt][nt], ah[mt], bb[nt]);
            // A-lo fragments; term 2: al * bh
#pragma unroll
            for (int mt = 0; mt < 2; mt++) {
                uint32_t r = wm * 32 + mt * 16 + (lane & 15);
                ldsm_x4(aw[mt], smb + SM_AL + r * 80 + ka);
            }
#pragma unroll
            for (int mt = 0; mt < 2; mt++)
#pragma unroll
                for (int nt = 0; nt < 8; nt++)
                    mma16816(acc[mt][nt], aw[mt], bb[nt]);
            // B-lo fragments (reuse bb); term 3: ah * bl
#pragma unroll
            for (int p = 0; p < 4; p++) {
                uint32_t r = wn * 64 + p * 16 + ((lane >> 4) & 1) * 8 + (lane & 7);
                uint32_t t4[4];
                ldsm_x4(t4, smb + SM_BL + r * 80 + kb);
                bb[2 * p][0] = t4[0]; bb[2 * p][1] = t4[1];
                bb[2 * p + 1][0] = t4[2]; bb[2 * p + 1][1] = t4[3];
            }
#pragma unroll
            for (int mt = 0; mt < 2; mt++)
#pragma unroll
                for (int nt = 0; nt < 8; nt++)
                    mma16816(acc[mt][nt], ah[mt], bb[nt]);
        }
    }

    // ---- epilogue: direct stores (c-frag layout) ---------------------------
#pragma unroll
    for (int mt = 0; mt < 2; mt++) {
        int row0 = brow + wm * 32 + mt * 16 + (lane >> 2);
#pragma unroll
        for (int nt = 0; nt < 8; nt++) {
            int col = bcol + wn * 64 + nt * 8 + (lane & 3) * 2;
            float b0 = bias[col], b1 = bias[col + 1];
#pragma unroll
            for (int h = 0; h < 2; h++) {
                int r = row0 + h * 8;
                float v0 = (acc[mt][nt][2 * h + 0] + b0) * scale;
                float v1 = (acc[mt][nt][2 * h + 1] + b1) * scale;
                if (ep) {
                    v0 = 0.5f * v0 * (1.f + erff(v0 * 0.70710678118654752f));
                    v1 = 0.5f * v1 * (1.f + erff(v1 * 0.70710678118654752f));
                }
                float2 vv = make_float2(v0, v1);
                *(float2*)&C[(size_t)r * N + col] = vv;
            }
        }
    }
}

__global__ __launch_bounds__(256) void gemm_mma_kernel(
    const float* __restrict__ A,
    const __nv_bfloat16* __restrict__ Bh, const __nv_bfloat16* __restrict__ Bl,
    const float* __restrict__ bias, float* __restrict__ C,
    int N, int K, int ep, float scale)
{
    gemm_mma_core(A, Bh, Bl, bias, C, N, K, ep, scale,
                  blockIdx.y * 128, blockIdx.x * 128);
}

// batched 5-projection GEMM (q,k,v,kg,vg) sharing A; N=768 each, K=768.
struct Proj5 {
    const __nv_bfloat16* bh[5];
    const __nv_bfloat16* bl[5];
    const float* bias[5];
    float* c[5];
};
__global__ __launch_bounds__(256) void gemm_mma_proj5_kernel(
    const float* __restrict__ A, Proj5 p)
{
    const int seg  = blockIdx.x / 6;
    const int bcol = (blockIdx.x % 6) * 128;
    const float scale = (seg == 0) ? 0.125f : 1.f;
    gemm_mma_core(A, p.bh[seg], p.bl[seg], p.bias[seg], p.c[seg], DD, DD, 0,
                  scale, blockIdx.y * 128, bcol);
}

// ---------------- weight transpose + hi/lo split -----------------------------
__global__ __launch_bounds__(256) void wt_conv_kernel(
    const float* __restrict__ W, __nv_bfloat16* __restrict__ oh,
    __nv_bfloat16* __restrict__ ol, int K, int N)
{
    __shared__ float ts[32][33];
    int nb = blockIdx.x * 32, kb = blockIdx.y * 32;
    int tx = threadIdx.x, ty = threadIdx.y;
#pragma unroll
    for (int i = ty; i < 32; i += 8)
        ts[i][tx] = W[(size_t)(kb + i) * N + nb + tx];
    __syncthreads();
#pragma unroll
    for (int i = ty; i < 32; i += 8) {
        float x = ts[tx][i];
        __nv_bfloat16 h = __float2bfloat16_rn(x);
        float lo = x - __bfloat162float(h);
        size_t o = (size_t)(nb + i) * K + kb + tx;
        oh[o] = h;
        ol[o] = __float2bfloat16_rn(lo);
    }
}

// ---------------- embedding gather ------------------------------------------
__global__ void embed_kernel(const int* __restrict__ src,
                             const float* __restrict__ tok,
                             const float* __restrict__ pos,
                             float* __restrict__ out)
{
    int row = blockIdx.x;
    int s = row % SS;
    int t = src[row];
    for (int i = threadIdx.x; i < DD; i += blockDim.x)
        out[(size_t)row * DD + i] = tok[(size_t)t * DD + i] + pos[(size_t)s * DD + i];
}

// ---------------- add + layernorm -------------------------------------------
__global__ __launch_bounds__(256) void add_ln_kernel(
    const float* __restrict__ x, const float* __restrict__ res,
    const float* __restrict__ gam, const float* __restrict__ bet,
    float* __restrict__ out)
{
    int row = blockIdx.x;
    int tid = threadIdx.x;
    const float* xr = x + (size_t)row * DD;
    const float* rr = res ? res + (size_t)row * DD : nullptr;
    float v[3];
    float lsum = 0.f, lsq = 0.f;
#pragma unroll
    for (int i = 0; i < 3; i++) {
        int idx = tid + i * 256;
        float t = xr[idx];
        if (rr) t += rr[idx];
        v[i] = t; lsum += t; lsq += t * t;
    }
    __shared__ float r1[256], r2[256];
    r1[tid] = lsum; r2[tid] = lsq;
    __syncthreads();
    for (int o = 128; o > 0; o >>= 1) {
        if (tid < o) { r1[tid] += r1[tid + o]; r2[tid] += r2[tid + o]; }
        __syncthreads();
    }
    float mean = r1[0] * (1.f / DD);
    float var  = r2[0] * (1.f / DD) - mean * mean;
    float inv  = rsqrtf(var + 1e-5f);
#pragma unroll
    for (int i = 0; i < 3; i++) {
        int idx = tid + i * 256;
        out[(size_t)row * DD + idx] = (v[i] - mean) * inv * gam[idx] + bet[idx];
    }
}

// ---------------- qg = (h[:,0] @ Wqg + bqg) / 8 ------------------------------
__global__ __launch_bounds__(128) void qg_kernel(
    const float* __restrict__ h, const float* __restrict__ W,
    const float* __restrict__ b, float* __restrict__ qg)
{
    __shared__ float hs[DD];
    int bb = blockIdx.x;
    for (int i = threadIdx.x; i < DD; i += 128)
        hs[i] = h[(size_t)bb * SS * DD + i];
    __syncthreads();
    int n = blockIdx.y * 128 + threadIdx.x;
    float acc = b[n];
#pragma unroll 4
    for (int k = 0; k < DD; k++) acc += hs[k] * W[(size_t)k * DD + n];
    qg[bb * DD + n] = acc * 0.125f;
}

// ---------------- sliding-window + global-slot attention ---------------------
__global__ __launch_bounds__(128) void sliding_attn_kernel(
    const float* __restrict__ q, const float* __restrict__ k,
    const float* __restrict__ v, const int* __restrict__ mask,
    float* __restrict__ outp)
{
    extern __shared__ float smd[];
    float* ks = smd;
    float* vs = smd + 128 * 64;

    const int c = blockIdx.x, hh = blockIdx.y, b = blockIdx.z;
    const int qi = threadIdx.x;
    const int t  = c * WW + qi;
    const size_t base = (size_t)(b * SS) * DD + hh * DH;

    float qr[DH];
#pragma unroll
    for (int d = 0; d < DH; d++)
        qr[d] = q[base + (size_t)t * DD + d];

    float m, l, acc[DH];
    {
        float sc;
        if (mask[b * SS + 0] != 0) {
            sc = 0.f;
#pragma unroll
            for (int d = 0; d < DH; d++)
                sc += qr[d] * k[base + d];
        } else sc = -1e9f;
        m = sc; l = 1.f;
#pragma unroll
        for (int d = 0; d < DH; d++) acc[d] = v[base + d];
    }

    for (int tile = 0; tile < 3; tile++) {
        int s0 = c * WW - WW + tile * WW;
        __syncthreads();
        for (int li = qi; li < 128 * 64; li += 128) {
            int j = li >> 6, d = li & 63;
            int srow = s0 + j;
            float kv = 0.f, vv = 0.f;
            if (srow >= 0 && srow < SS) {
                kv = k[base + (size_t)srow * DD + d];
                vv = v[base + (size_t)srow * DD + d];
            }
            ks[j * 64 + d] = kv;
            vs[j * 64 + d] = vv;
        }
        __syncthreads();

        for (int j = 0; j < 128; j++) {
            int jj = tile * 128 + j;
            if (jj < qi || jj > qi + 2 * WW) continue;
            int srow = s0 + j;
            if (srow < 0 || srow >= SS) continue;
            if (mask[b * SS + srow] == 0) continue;
            float sc = 0.f;
#pragma unroll
            for (int d = 0; d < DH; d++)
                sc += qr[d] * ks[j * 64 + d];
            if (sc > m) {
                float f = expf(m - sc);
                l *= f;
#pragma unroll
                for (int d = 0; d < DH; d++) acc[d] *= f;
                m = sc;
            }
            float w = expf(sc - m);
            l += w;
#pragma unroll
            for (int d = 0; d < DH; d++) acc[d] += w * vs[j * 64 + d];
        }
    }

    float invl = 1.f / l;
#pragma unroll
    for (int d = 0; d < DH; d++)
        outp[base + (size_t)t * DD + d] = acc[d] * invl;
}

// ---------------- global attention for token 0 -------------------------------
__global__ __launch_bounds__(256) void global_attn_kernel(
    const float* __restrict__ qg, const float* __restrict__ kg,
    const float* __restrict__ vg, const int* __restrict__ mask,
    float* __restrict__ outp)
{
    __shared__ float sc[SS];
    __shared__ float red[256];
    const int hh = blockIdx.x, b = blockIdx.y;
    const int tid = threadIdx.x;
    const size_t base = (size_t)(b * SS) * DD + hh * DH;

    float qr[DH];
#pragma unroll
    for (int d = 0; d < DH; d++) qr[d] = qg[b * DD + hh * DH + d];

    for (int s = tid; s < SS; s += 256) {
        float d0;
        if (mask[b * SS + s] != 0) {
            d0 = 0.f;
#pragma unroll
            for (int d = 0; d < DH; d++)
                d0 += qr[d] * kg[base + (size_t)s * DD + d];
        } else d0 = -1e9f;
        sc[s] = d0;
    }
    __syncthreads();

    float mx = -1e30f;
    for (int s = tid; s < SS; s += 256) mx = fmaxf(mx, sc[s]);
    red[tid] = mx; __syncthreads();
    for (int o = 128; o > 0; o >>= 1) {
        if (tid < o) red[tid] = fmaxf(red[tid], red[tid + o]);
        __syncthreads();
    }
    mx = red[0];
    __syncthreads();

    float ps = 0.f;
    for (int s = tid; s < SS; s += 256) {
        float e = expf(sc[s] - mx);
        sc[s] = e; ps += e;
    }
    red[tid] = ps; __syncthreads();
    for (int o = 128; o > 0; o >>= 1) {
        if (tid < o) red[tid] += red[tid + o];
        __syncthreads();
    }
    float total = red[0];
    __syncthreads();

    int d = tid & 63, g = tid >> 6;
    float a = 0.f;
    for (int s = g; s < SS; s += 4)
        a += sc[s] * vg[base + (size_t)s * DD + d];
    red[tid] = a; __syncthreads();
    if (g == 0) {
        a = red[tid] + red[tid + 64] + red[tid + 128] + red[tid + 192];
        outp[base + d] = a / total;
    }
}

// ---------------- classifier head -------------------------------------------
__global__ void cls_kernel(const float* __restrict__ h,
                           const float* __restrict__ Wc,
                           const float* __restrict__ bc,
                           const int* __restrict__ mask,
                           float* __restrict__ out)
{
    int tid = threadIdx.x;
    if (tid < BB * 3) {
        int b = tid / 3, j = tid % 3;
        const float* hr = h + (size_t)b * SS * DD;
        float acc = bc[j];
        for (int kx = 0; kx < DD; kx++) acc += hr[kx] * Wc[kx * 3 + j];
        float sg = 1.f / (1.f + expf(-acc));
        out[j * BB + b] = sg;
        if (j == 0) out[3 * BB + b] = (float)mask[b * SS + 0];
    }
}

// ---------------- host orchestration -----------------------------------------
extern "C" void kernel_launch(void* const* d_in, const int* in_sizes, int n_in,
                              void* d_out, int out_size)
{
    const int*   src      = (const int*)  d_in[0];
    const int*   mask_src = (const int*)  d_in[1];
    const float* emb_tok  = (const float*)d_in[3];
    const float* emb_pos  = (const float*)d_in[4];
    const float* emb_ln_s = (const float*)d_in[5];
    const float* emb_ln_b = (const float*)d_in[6];
    const float* Wq  = (const float*)d_in[7];
    const float* bq  = (const float*)d_in[8];
    const float* Wk  = (const float*)d_in[9];
    const float* bk  = (const float*)d_in[10];
    const float* Wv  = (const float*)d_in[11];
    const float* bv  = (const float*)d_in[12];
    const float* Wo  = (const float*)d_in[13];
    const float* bo  = (const float*)d_in[14];
    const float* Wqg = (const float*)d_in[15];
    const float* bqg = (const float*)d_in[16];
    const float* Wkg = (const float*)d_in[17];
    const float* bkg = (const float*)d_in[18];
    const float* Wvg = (const float*)d_in[19];
    const float* bvg = (const float*)d_in[20];
    const float* ln1_s = (const float*)d_in[21];
    const float* ln1_b = (const float*)d_in[22];
    const float* W1  = (const float*)d_in[23];
    const float* b1  = (const float*)d_in[24];
    const float* W2  = (const float*)d_in[25];
    const float* b2  = (const float*)d_in[26];
    const float* ln2_s = (const float*)d_in[27];
    const float* ln2_b = (const float*)d_in[28];
    const float* Wcls = (const float*)d_in[29];
    const float* bcls = (const float*)d_in[30];
    float* out = (float*)d_out;

    float *p_h, *p_q, *p_k, *p_v, *p_kg, *p_vg, *p_a, *p_t, *p_ff, *p_qg;
    __nv_bfloat16 *p_wh, *p_wl;
    cudaGetSymbolAddress((void**)&p_h,  g_h);
    cudaGetSymbolAddress((void**)&p_q,  g_q);
    cudaGetSymbolAddress((void**)&p_k,  g_k);
    cudaGetSymbolAddress((void**)&p_v,  g_v);
    cudaGetSymbolAddress((void**)&p_kg, g_kg);
    cudaGetSymbolAddress((void**)&p_vg, g_vg);
    cudaGetSymbolAddress((void**)&p_a,  g_a);
    cudaGetSymbolAddress((void**)&p_t,  g_t);
    cudaGetSymbolAddress((void**)&p_ff, g_ff);
    cudaGetSymbolAddress((void**)&p_qg, g_qg);
    cudaGetSymbolAddress((void**)&p_wh, g_wt_h);
    cudaGetSymbolAddress((void**)&p_wl, g_wt_l);

    static const size_t SLIDE_SMEM = (2 * 128 * 64) * sizeof(float);
    cudaFuncSetAttribute(sliding_attn_kernel,
                         cudaFuncAttributeMaxDynamicSharedMemorySize,
                         (int)SLIDE_SMEM);

    // ---- weight transpose + split ----
    const size_t OFF_W1 = 6 * (size_t)WT_MAT;
    const size_t OFF_W2 = OFF_W1 + (size_t)DD * FFD;
    {
        dim3 blk(32, 8);
        for (int l = 0; l < LL; l++) {
            size_t lb = (size_t)l * WT_LAYER;
            const float* srcs[6] = {Wq, Wk, Wv, Wkg, Wvg, Wo};
            for (int mi = 0; mi < 6; mi++) {
                size_t o = lb + (size_t)mi * WT_MAT;
                wt_conv_kernel<<<dim3(DD / 32, DD / 32), blk>>>(
                    srcs[mi] + (size_t)l * DD * DD, p_wh + o, p_wl + o, DD, DD);
            }
            wt_conv_kernel<<<dim3(FFD / 32, DD / 32), blk>>>(
                W1 + (size_t)l * DD * FFD, p_wh + lb + OFF_W1, p_wl + lb + OFF_W1,
                DD, FFD);
            wt_conv_kernel<<<dim3(DD / 32, FFD / 32), blk>>>(
                W2 + (size_t)l * FFD * DD, p_wh + lb + OFF_W2, p_wl + lb + OFF_W2,
                FFD, DD);
        }
    }

    // embedding + LN
    embed_kernel<<<NTOK, 256>>>(src, emb_tok, emb_pos, p_t);
    add_ln_kernel<<<NTOK, 256>>>(p_t, nullptr, emb_ln_s, emb_ln_b, p_h);

    for (int l = 0; l < LL; l++) {
        const size_t lb  = (size_t)l * WT_LAYER;
        const size_t bo_ = (size_t)l * DD;

        // batched projections (q scaled by 0.125 in seg 0)
        Proj5 p;
        const float* biases[5] = {bq + bo_, bk + bo_, bv + bo_, bkg + bo_, bvg + bo_};
        float* outs[5] = {p_q, p_k, p_v, p_kg, p_vg};
        for (int s = 0; s < 5; s++) {
            p.bh[s] = p_wh + lb + (size_t)s * WT_MAT;
            p.bl[s] = p_wl + lb + (size_t)s * WT_MAT;
            p.bias[s] = biases[s];
            p.c[s] = outs[s];
        }
        gemm_mma_proj5_kernel<<<dim3(30, NTOK / 128), 256>>>(p_h, p);
        qg_kernel<<<dim3(BB, 6), 128>>>(p_h, Wqg + (size_t)l * DD * DD, bqg + bo_, p_qg);

        // attention
        sliding_attn_kernel<<<dim3(NC, HH, BB), 128, SLIDE_SMEM>>>(
            p_q, p_k, p_v, mask_src, p_a);
        global_attn_kernel<<<dim3(HH, BB), 256>>>(
            p_qg, p_kg, p_vg, mask_src, p_a);

        // output proj + residual LN
        gemm_mma_kernel<<<dim3(6, NTOK / 128), 256>>>(
            p_a, p_wh + lb + 5 * (size_t)WT_MAT, p_wl + lb + 5 * (size_t)WT_MAT,
            bo + bo_, p_t, DD, DD, 0, 1.f);
        add_ln_kernel<<<NTOK, 256>>>(p_t, p_h, ln1_s + bo_, ln1_b + bo_, p_h);

        // FFN
        gemm_mma_kernel<<<dim3(FFD / 128, NTOK / 128), 256>>>(
            p_h, p_wh + lb + OFF_W1, p_wl + lb + OFF_W1,
            b1 + (size_t)l * FFD, p_ff, FFD, DD, 1, 1.f);
        gemm_mma_kernel<<<dim3(6, NTOK / 128), 256>>>(
            p_ff, p_wh + lb + OFF_W2, p_wl + lb + OFF_W2,
            b2 + bo_, p_t, DD, FFD, 0, 1.f);
        add_ln_kernel<<<NTOK, 256>>>(p_t, p_h, ln2_s + bo_, ln2_b + bo_, p_h);
    }

    cls_kernel<<<1, 32>>>(p_h, Wcls, bcls, mask_src, out);
}

// round 13
// speedup vs baseline: 1.8351x; 1.0589x over previous
#include <cuda_runtime.h>
#include <cuda_bf16.h>
#include <math.h>
#include <stdint.h>

// Problem constants (fixed inputs)
#define BB 2
#define SS 2048
#define DD 768
#define HH 12
#define DH 64
#define WW 128
#define NC (SS / WW)      // 16
#define LL 4
#define FFD 3072
#define NTOK (BB * SS)    // 4096

// ---------------- scratch (device globals; no allocation allowed) ----------
__device__ float g_h [NTOK * DD];
__device__ float g_q [NTOK * DD];
__device__ float g_k [NTOK * DD];
__device__ float g_v [NTOK * DD];
__device__ float g_kg[NTOK * DD];
__device__ float g_vg[NTOK * DD];
__device__ float g_a [NTOK * DD];
__device__ float g_t [NTOK * DD];
__device__ float g_qg[BB * DD];

// split bf16 activations
__device__ __align__(16) __nv_bfloat16 g_hh [NTOK * DD];
__device__ __align__(16) __nv_bfloat16 g_hl [NTOK * DD];
__device__ __align__(16) __nv_bfloat16 g_ahh[NTOK * DD];
__device__ __align__(16) __nv_bfloat16 g_ahl[NTOK * DD];
__device__ __align__(16) __nv_bfloat16 g_ffh[NTOK * FFD];
__device__ __align__(16) __nv_bfloat16 g_ffl[NTOK * FFD];

// transposed/split bf16 weights: per layer 6x(768x768) + w1(3072x768) + w2(768x3072)
#define WT_MAT   (DD * DD)
#define WT_LAYER (6 * WT_MAT + 2 * DD * FFD)
__device__ __align__(16) __nv_bfloat16 g_wt_h[LL * WT_LAYER];
__device__ __align__(16) __nv_bfloat16 g_wt_l[LL * WT_LAYER];

// ================= helpers ==================================================
__device__ __forceinline__ uint32_t smem_u32(const void* p) {
    uint32_t a;
    asm("{ .reg .u64 t; cvta.to.shared.u64 t, %1; cvt.u32.u64 %0, t; }"
        : "=r"(a) : "l"(p));
    return a;
}
__device__ __forceinline__ void ldsm_x4(uint32_t* r, uint32_t addr) {
    asm volatile("ldmatrix.sync.aligned.m8n8.x4.shared.b16 {%0,%1,%2,%3}, [%4];"
                 : "=r"(r[0]), "=r"(r[1]), "=r"(r[2]), "=r"(r[3]) : "r"(addr));
}
__device__ __forceinline__ void mma16816(float* d, const uint32_t* a,
                                         const uint32_t* b) {
    asm volatile("mma.sync.aligned.m16n8k16.row.col.f32.bf16.bf16.f32 "
                 "{%0,%1,%2,%3}, {%4,%5,%6,%7}, {%8,%9}, {%0,%1,%2,%3};"
                 : "+f"(d[0]), "+f"(d[1]), "+f"(d[2]), "+f"(d[3])
                 : "r"(a[0]), "r"(a[1]), "r"(a[2]), "r"(a[3]),
                   "r"(b[0]), "r"(b[1]));
}
#define CP_ASYNC16(dst, src) \
    asm volatile("cp.async.cg.shared.global [%0], [%1], 16;" \
                 :: "r"(dst), "l"(src))
#define CP_COMMIT() asm volatile("cp.async.commit_group;" ::: "memory")
#define CP_WAIT1()  asm volatile("cp.async.wait_group 1;" ::: "memory")
#define CP_WAIT0()  asm volatile("cp.async.wait_group 0;" ::: "memory")

// ================= mma.sync GEMM (cp.async double-buffered) =================
// C = (A @ W + bias) * scale (+gelu).  A given pre-split as Ah/Al [M,K] bf16;
// W pre-transposed+split as Bh/Bl [N,K] bf16.  CTA tile 128x128, 8 warps
// (4m x 2n), warp tile 32x64, K-chunk 32.  3 terms: ah*bh + al*bh + ah*bl.
// smem rows 80B pitch (64B data + 16B pad) -> conflict-free ldmatrix.
// Output: fp32 C, or split bf16 (Ch,Cl) when Cl != nullptr.
#define SM_AH 0
#define SM_AL 10240
#define SM_BH 20480
#define SM_BL 30720
#define SM_BUF 40960
#define SM_TOT (2 * SM_BUF)   // 81920 dynamic

__device__ __forceinline__ void gemm_mma_core(
    const __nv_bfloat16* __restrict__ Ah, const __nv_bfloat16* __restrict__ Al,
    const __nv_bfloat16* __restrict__ Bh, const __nv_bfloat16* __restrict__ Bl,
    const float* __restrict__ bias, float* __restrict__ C,
    __nv_bfloat16* __restrict__ Ch, __nv_bfloat16* __restrict__ Cl,
    int N, int K, int ep, float scale, int brow, int bcol, char* sm)
{
    const uint32_t smb = smem_u32(sm);
    const int tid  = threadIdx.x;
    const int lane = tid & 31, wrp = tid >> 5;
    const int wm = wrp >> 1, wn = wrp & 1;       // 4x2 warp grid

    float acc[2][8][4];
#pragma unroll
    for (int mt = 0; mt < 2; mt++)
#pragma unroll
        for (int nt = 0; nt < 8; nt++)
#pragma unroll
            for (int j = 0; j < 4; j++) acc[mt][nt][j] = 0.f;

    const int nch = K >> 5;

    // ---- async stage of one 32-k chunk into buffer bb ----------------------
    auto load_chunk = [&](int ch, int bb) {
        const int k0 = ch << 5;
        const uint32_t base = smb + bb * SM_BUF;
#pragma unroll
        for (int i = 0; i < 2; i++) {
            int idx = tid + i * 256;
            int row = idx >> 2, seg = idx & 3;
            uint32_t off = row * 80 + seg * 16;
            size_t ga = (size_t)(brow + row) * K + k0 + seg * 8;
            size_t gb = (size_t)(bcol + row) * K + k0 + seg * 8;
            CP_ASYNC16(base + SM_AH + off, &Ah[ga]);
            CP_ASYNC16(base + SM_AL + off, &Al[ga]);
            CP_ASYNC16(base + SM_BH + off, &Bh[gb]);
            CP_ASYNC16(base + SM_BL + off, &Bl[gb]);
        }
        CP_COMMIT();
    };

    load_chunk(0, 0);
    for (int ch = 0; ch < nch; ch++) {
        if (ch + 1 < nch) { load_chunk(ch + 1, (ch + 1) & 1); CP_WAIT1(); }
        else              { CP_WAIT0(); }
        __syncthreads();
        const uint32_t base = smb + (ch & 1) * SM_BUF;

#pragma unroll
        for (int ks = 0; ks < 2; ks++) {
            const uint32_t kb = ks * 32 + ((lane >> 3) & 1) * 16;  // B k-byte
            const uint32_t ka = ks * 32 + (lane >> 4) * 16;        // A k-byte
            uint32_t ah[2][4], aw[2][4], bb[8][2];
            // A-hi fragments
#pragma unroll
            for (int mt = 0; mt < 2; mt++) {
                uint32_t r = wm * 32 + mt * 16 + (lane & 15);
                ldsm_x4(ah[mt], base + SM_AH + r * 80 + ka);
            }
            // B-hi fragments (pairs of n8 tiles)
#pragma unroll
            for (int p = 0; p < 4; p++) {
                uint32_t r = wn * 64 + p * 16 + ((lane >> 4) & 1) * 8 + (lane & 7);
                uint32_t t4[4];
                ldsm_x4(t4, base + SM_BH + r * 80 + kb);
                bb[2 * p][0] = t4[0]; bb[2 * p][1] = t4[1];
                bb[2 * p + 1][0] = t4[2]; bb[2 * p + 1][1] = t4[3];
            }
            // term 1: ah * bh
#pragma unroll
            for (int mt = 0; mt < 2; mt++)
#pragma unroll
                for (int nt = 0; nt < 8; nt++)
                    mma16816(acc[mt][nt], ah[mt], bb[nt]);
            // A-lo fragments; term 2: al * bh
#pragma unroll
            for (int mt = 0; mt < 2; mt++) {
                uint32_t r = wm * 32 + mt * 16 + (lane & 15);
                ldsm_x4(aw[mt], base + SM_AL + r * 80 + ka);
            }
#pragma unroll
            for (int mt = 0; mt < 2; mt++)
#pragma unroll
                for (int nt = 0; nt < 8; nt++)
                    mma16816(acc[mt][nt], aw[mt], bb[nt]);
            // B-lo fragments (reuse bb); term 3: ah * bl
#pragma unroll
            for (int p = 0; p < 4; p++) {
                uint32_t r = wn * 64 + p * 16 + ((lane >> 4) & 1) * 8 + (lane & 7);
                uint32_t t4[4];
                ldsm_x4(t4, base + SM_BL + r * 80 + kb);
                bb[2 * p][0] = t4[0]; bb[2 * p][1] = t4[1];
                bb[2 * p + 1][0] = t4[2]; bb[2 * p + 1][1] = t4[3];
            }
#pragma unroll
            for (int mt = 0; mt < 2; mt++)
#pragma unroll
                for (int nt = 0; nt < 8; nt++)
                    mma16816(acc[mt][nt], ah[mt], bb[nt]);
        }
        __syncthreads();
    }

    // ---- epilogue: direct stores (c-frag layout) ---------------------------
#pragma unroll
    for (int mt = 0; mt < 2; mt++) {
        int row0 = brow + wm * 32 + mt * 16 + (lane >> 2);
#pragma unroll
        for (int nt = 0; nt < 8; nt++) {
            int col = bcol + wn * 64 + nt * 8 + (lane & 3) * 2;
            float b0 = bias[col], b1 = bias[col + 1];
#pragma unroll
            for (int h = 0; h < 2; h++) {
                int r = row0 + h * 8;
                float v0 = (acc[mt][nt][2 * h + 0] + b0) * scale;
                float v1 = (acc[mt][nt][2 * h + 1] + b1) * scale;
                if (ep) {
                    v0 = 0.5f * v0 * (1.f + erff(v0 * 0.70710678118654752f));
                    v1 = 0.5f * v1 * (1.f + erff(v1 * 0.70710678118654752f));
                }
                if (Cl) {
                    __nv_bfloat16 h0 = __float2bfloat16_rn(v0);
                    __nv_bfloat16 h1 = __float2bfloat16_rn(v1);
                    __nv_bfloat162 hp; hp.x = h0; hp.y = h1;
                    *(__nv_bfloat162*)&Ch[(size_t)r * N + col] = hp;
                    __nv_bfloat162 lp;
                    lp.x = __float2bfloat16_rn(v0 - __bfloat162float(h0));
                    lp.y = __float2bfloat16_rn(v1 - __bfloat162float(h1));
                    *(__nv_bfloat162*)&Cl[(size_t)r * N + col] = lp;
                } else {
                    *(float2*)&C[(size_t)r * N + col] = make_float2(v0, v1);
                }
            }
        }
    }
}

__global__ __launch_bounds__(256) void gemm_mma_kernel(
    const __nv_bfloat16* __restrict__ Ah, const __nv_bfloat16* __restrict__ Al,
    const __nv_bfloat16* __restrict__ Bh, const __nv_bfloat16* __restrict__ Bl,
    const float* __restrict__ bias, float* __restrict__ C,
    __nv_bfloat16* Ch, __nv_bfloat16* Cl,
    int N, int K, int ep, float scale)
{
    extern __shared__ char sm[];
    gemm_mma_core(Ah, Al, Bh, Bl, bias, C, Ch, Cl, N, K, ep, scale,
                  blockIdx.y * 128, blockIdx.x * 128, sm);
}

// batched 5-projection GEMM (q,k,v,kg,vg) sharing A; N=768 each, K=768.
struct Proj5 {
    const __nv_bfloat16* bh[5];
    const __nv_bfloat16* bl[5];
    const float* bias[5];
    float* c[5];
};
__global__ __launch_bounds__(256) void gemm_mma_proj5_kernel(
    const __nv_bfloat16* __restrict__ Ah, const __nv_bfloat16* __restrict__ Al,
    Proj5 p)
{
    extern __shared__ char sm[];
    const int seg  = blockIdx.x / 6;
    const int bcol = (blockIdx.x % 6) * 128;
    const float scale = (seg == 0) ? 0.125f : 1.f;
    gemm_mma_core(Ah, Al, p.bh[seg], p.bl[seg], p.bias[seg], p.c[seg],
                  nullptr, nullptr, DD, DD, 0, scale,
                  blockIdx.y * 128, bcol, sm);
}

// ---------------- weight transpose + hi/lo split -----------------------------
__global__ __launch_bounds__(256) void wt_conv_kernel(
    const float* __restrict__ W, __nv_bfloat16* __restrict__ oh,
    __nv_bfloat16* __restrict__ ol, int K, int N)
{
    __shared__ float ts[32][33];
    int nb = blockIdx.x * 32, kb = blockIdx.y * 32;
    int tx = threadIdx.x, ty = threadIdx.y;
#pragma unroll
    for (int i = ty; i < 32; i += 8)
        ts[i][tx] = W[(size_t)(kb + i) * N + nb + tx];
    __syncthreads();
#pragma unroll
    for (int i = ty; i < 32; i += 8) {
        float x = ts[tx][i];
        __nv_bfloat16 h = __float2bfloat16_rn(x);
        float lo = x - __bfloat162float(h);
        size_t o = (size_t)(nb + i) * K + kb + tx;
        oh[o] = h;
        ol[o] = __float2bfloat16_rn(lo);
    }
}

// ---------------- activation split (fp32 -> bf16 hi/lo) ----------------------
__global__ __launch_bounds__(256) void act_conv_kernel(
    const float* __restrict__ x, __nv_bfloat16* __restrict__ oh,
    __nv_bfloat16* __restrict__ ol, int n4)
{
    int idx = blockIdx.x * 256 + threadIdx.x;
    if (idx >= n4) return;
    float4 v = ((const float4*)x)[idx];
    __nv_bfloat16 h0 = __float2bfloat16_rn(v.x);
    __nv_bfloat16 h1 = __float2bfloat16_rn(v.y);
    __nv_bfloat16 h2 = __float2bfloat16_rn(v.z);
    __nv_bfloat16 h3 = __float2bfloat16_rn(v.w);
    __nv_bfloat162 hp0; hp0.x = h0; hp0.y = h1;
    __nv_bfloat162 hp1; hp1.x = h2; hp1.y = h3;
    ((__nv_bfloat162*)oh)[idx * 2 + 0] = hp0;
    ((__nv_bfloat162*)oh)[idx * 2 + 1] = hp1;
    __nv_bfloat162 lp0, lp1;
    lp0.x = __float2bfloat16_rn(v.x - __bfloat162float(h0));
    lp0.y = __float2bfloat16_rn(v.y - __bfloat162float(h1));
    lp1.x = __float2bfloat16_rn(v.z - __bfloat162float(h2));
    lp1.y = __float2bfloat16_rn(v.w - __bfloat162float(h3));
    ((__nv_bfloat162*)ol)[idx * 2 + 0] = lp0;
    ((__nv_bfloat162*)ol)[idx * 2 + 1] = lp1;
}

// ---------------- embedding gather ------------------------------------------
__global__ void embed_kernel(const int* __restrict__ src,
                             const float* __restrict__ tok,
                             const float* __restrict__ pos,
                             float* __restrict__ out)
{
    int row = blockIdx.x;
    int s = row % SS;
    int t = src[row];
    for (int i = threadIdx.x; i < DD; i += blockDim.x)
        out[(size_t)row * DD + i] = tok[(size_t)t * DD + i] + pos[(size_t)s * DD + i];
}

// ---------------- add + layernorm (emits fp32 + split bf16) ------------------
__global__ __launch_bounds__(256) void add_ln_kernel(
    const float* __restrict__ x, const float* __restrict__ res,
    const float* __restrict__ gam, const float* __restrict__ bet,
    float* __restrict__ out,
    __nv_bfloat16* __restrict__ oh, __nv_bfloat16* __restrict__ ol)
{
    int row = blockIdx.x;
    int tid = threadIdx.x;
    const float* xr = x + (size_t)row * DD;
    const float* rr = res ? res + (size_t)row * DD : nullptr;
    float v[3];
    float lsum = 0.f, lsq = 0.f;
#pragma unroll
    for (int i = 0; i < 3; i++) {
        int idx = tid + i * 256;
        float t = xr[idx];
        if (rr) t += rr[idx];
        v[i] = t; lsum += t; lsq += t * t;
    }
    __shared__ float r1[256], r2[256];
    r1[tid] = lsum; r2[tid] = lsq;
    __syncthreads();
    for (int o = 128; o > 0; o >>= 1) {
        if (tid < o) { r1[tid] += r1[tid + o]; r2[tid] += r2[tid + o]; }
        __syncthreads();
    }
    float mean = r1[0] * (1.f / DD);
    float var  = r2[0] * (1.f / DD) - mean * mean;
    float inv  = rsqrtf(var + 1e-5f);
#pragma unroll
    for (int i = 0; i < 3; i++) {
        int idx = tid + i * 256;
        size_t o = (size_t)row * DD + idx;
        float vv = (v[i] - mean) * inv * gam[idx] + bet[idx];
        out[o] = vv;
        __nv_bfloat16 hb = __float2bfloat16_rn(vv);
        oh[o] = hb;
        ol[o] = __float2bfloat16_rn(vv - __bfloat162float(hb));
    }
}

// ---------------- qg = (h[:,0] @ Wqg + bqg) / 8 ------------------------------
__global__ __launch_bounds__(128) void qg_kernel(
    const float* __restrict__ h, const float* __restrict__ W,
    const float* __restrict__ b, float* __restrict__ qg)
{
    __shared__ float hs[DD];
    int bb = blockIdx.x;
    for (int i = threadIdx.x; i < DD; i += 128)
        hs[i] = h[(size_t)bb * SS * DD + i];
    __syncthreads();
    int n = blockIdx.y * 128 + threadIdx.x;
    float acc = b[n];
#pragma unroll 4
    for (int k = 0; k < DD; k++) acc += hs[k] * W[(size_t)k * DD + n];
    qg[bb * DD + n] = acc * 0.125f;
}

// ---------------- sliding-window + global-slot attention ---------------------
__global__ __launch_bounds__(128) void sliding_attn_kernel(
    const float* __restrict__ q, const float* __restrict__ k,
    const float* __restrict__ v, const int* __restrict__ mask,
    float* __restrict__ outp)
{
    extern __shared__ float smd[];
    float* ks = smd;
    float* vs = smd + 128 * 64;

    const int c = blockIdx.x, hh = blockIdx.y, b = blockIdx.z;
    const int qi = threadIdx.x;
    const int t  = c * WW + qi;
    const size_t base = (size_t)(b * SS) * DD + hh * DH;

    float qr[DH];
#pragma unroll
    for (int d = 0; d < DH; d++)
        qr[d] = q[base + (size_t)t * DD + d];

    float m, l, acc[DH];
    {
        float sc;
        if (mask[b * SS + 0] != 0) {
            sc = 0.f;
#pragma unroll
            for (int d = 0; d < DH; d++)
                sc += qr[d] * k[base + d];
        } else sc = -1e9f;
        m = sc; l = 1.f;
#pragma unroll
        for (int d = 0; d < DH; d++) acc[d] = v[base + d];
    }

    for (int tile = 0; tile < 3; tile++) {
        int s0 = c * WW - WW + tile * WW;
        __syncthreads();
        for (int li = qi; li < 128 * 64; li += 128) {
            int j = li >> 6, d = li & 63;
            int srow = s0 + j;
            float kv = 0.f, vv = 0.f;
            if (srow >= 0 && srow < SS) {
                kv = k[base + (size_t)srow * DD + d];
                vv = v[base + (size_t)srow * DD + d];
            }
            ks[j * 64 + d] = kv;
            vs[j * 64 + d] = vv;
        }
        __syncthreads();

        for (int j = 0; j < 128; j++) {
            int jj = tile * 128 + j;
            if (jj < qi || jj > qi + 2 * WW) continue;
            int srow = s0 + j;
            if (srow < 0 || srow >= SS) continue;
            if (mask[b * SS + srow] == 0) continue;
            float sc = 0.f;
#pragma unroll
            for (int d = 0; d < DH; d++)
                sc += qr[d] * ks[j * 64 + d];
            if (sc > m) {
                float f = expf(m - sc);
                l *= f;
#pragma unroll
                for (int d = 0; d < DH; d++) acc[d] *= f;
                m = sc;
            }
            float w = expf(sc - m);
            l += w;
#pragma unroll
            for (int d = 0; d < DH; d++) acc[d] += w * vs[j * 64 + d];
        }
    }

    float invl = 1.f / l;
#pragma unroll
    for (int d = 0; d < DH; d++)
        outp[base + (size_t)t * DD + d] = acc[d] * invl;
}

// ---------------- global attention for token 0 -------------------------------
__global__ __launch_bounds__(256) void global_attn_kernel(
    const float* __restrict__ qg, const float* __restrict__ kg,
    const float* __restrict__ vg, const int* __restrict__ mask,
    float* __restrict__ outp)
{
    __shared__ float sc[SS];
    __shared__ float red[256];
    const int hh = blockIdx.x, b = blockIdx.y;
    const int tid = threadIdx.x;
    const size_t base = (size_t)(b * SS) * DD + hh * DH;

    float qr[DH];
#pragma unroll
    for (int d = 0; d < DH; d++) qr[d] = qg[b * DD + hh * DH + d];

    for (int s = tid; s < SS; s += 256) {
        float d0;
        if (mask[b * SS + s] != 0) {
            d0 = 0.f;
#pragma unroll
            for (int d = 0; d < DH; d++)
                d0 += qr[d] * kg[base + (size_t)s * DD + d];
        } else d0 = -1e9f;
        sc[s] = d0;
    }
    __syncthreads();

    float mx = -1e30f;
    for (int s = tid; s < SS; s += 256) mx = fmaxf(mx, sc[s]);
    red[tid] = mx; __syncthreads();
    for (int o = 128; o > 0; o >>= 1) {
        if (tid < o) red[tid] = fmaxf(red[tid], red[tid + o]);
        __syncthreads();
    }
    mx = red[0];
    __syncthreads();

    float ps = 0.f;
    for (int s = tid; s < SS; s += 256) {
        float e = expf(sc[s] - mx);
        sc[s] = e; ps += e;
    }
    red[tid] = ps; __syncthreads();
    for (int o = 128; o > 0; o >>= 1) {
        if (tid < o) red[tid] += red[tid + o];
        __syncthreads();
    }
    float total = red[0];
    __syncthreads();

    int d = tid & 63, g = tid >> 6;
    float a = 0.f;
    for (int s = g; s < SS; s += 4)
        a += sc[s] * vg[base + (size_t)s * DD + d];
    red[tid] = a; __syncthreads();
    if (g == 0) {
        a = red[tid] + red[tid + 64] + red[tid + 128] + red[tid + 192];
        outp[base + d] = a / total;
    }
}

// ---------------- classifier head -------------------------------------------
__global__ void cls_kernel(const float* __restrict__ h,
                           const float* __restrict__ Wc,
                           const float* __restrict__ bc,
                           const int* __restrict__ mask,
                           float* __restrict__ out)
{
    int tid = threadIdx.x;
    if (tid < BB * 3) {
        int b = tid / 3, j = tid % 3;
        const float* hr = h + (size_t)b * SS * DD;
        float acc = bc[j];
        for (int kx = 0; kx < DD; kx++) acc += hr[kx] * Wc[kx * 3 + j];
        float sg = 1.f / (1.f + expf(-acc));
        out[j * BB + b] = sg;
        if (j == 0) out[3 * BB + b] = (float)mask[b * SS + 0];
    }
}

// ---------------- host orchestration -----------------------------------------
extern "C" void kernel_launch(void* const* d_in, const int* in_sizes, int n_in,
                              void* d_out, int out_size)
{
    const int*   src      = (const int*)  d_in[0];
    const int*   mask_src = (const int*)  d_in[1];
    const float* emb_tok  = (const float*)d_in[3];
    const float* emb_pos  = (const float*)d_in[4];
    const float* emb_ln_s = (const float*)d_in[5];
    const float* emb_ln_b = (const float*)d_in[6];
    const float* Wq  = (const float*)d_in[7];
    const float* bq  = (const float*)d_in[8];
    const float* Wk  = (const float*)d_in[9];
    const float* bk  = (const float*)d_in[10];
    const float* Wv  = (const float*)d_in[11];
    const float* bv  = (const float*)d_in[12];
    const float* Wo  = (const float*)d_in[13];
    const float* bo  = (const float*)d_in[14];
    const float* Wqg = (const float*)d_in[15];
    const float* bqg = (const float*)d_in[16];
    const float* Wkg = (const float*)d_in[17];
    const float* bkg = (const float*)d_in[18];
    const float* Wvg = (const float*)d_in[19];
    const float* bvg = (const float*)d_in[20];
    const float* ln1_s = (const float*)d_in[21];
    const float* ln1_b = (const float*)d_in[22];
    const float* W1  = (const float*)d_in[23];
    const float* b1  = (const float*)d_in[24];
    const float* W2  = (const float*)d_in[25];
    const float* b2  = (const float*)d_in[26];
    const float* ln2_s = (const float*)d_in[27];
    const float* ln2_b = (const float*)d_in[28];
    const float* Wcls = (const float*)d_in[29];
    const float* bcls = (const float*)d_in[30];
    float* out = (float*)d_out;

    float *p_h, *p_q, *p_k, *p_v, *p_kg, *p_vg, *p_a, *p_t, *p_qg;
    __nv_bfloat16 *p_wh, *p_wl, *p_hh, *p_hl, *p_ahh, *p_ahl, *p_ffh, *p_ffl;
    cudaGetSymbolAddress((void**)&p_h,  g_h);
    cudaGetSymbolAddress((void**)&p_q,  g_q);
    cudaGetSymbolAddress((void**)&p_k,  g_k);
    cudaGetSymbolAddress((void**)&p_v,  g_v);
    cudaGetSymbolAddress((void**)&p_kg, g_kg);
    cudaGetSymbolAddress((void**)&p_vg, g_vg);
    cudaGetSymbolAddress((void**)&p_a,  g_a);
    cudaGetSymbolAddress((void**)&p_t,  g_t);
    cudaGetSymbolAddress((void**)&p_qg, g_qg);
    cudaGetSymbolAddress((void**)&p_wh, g_wt_h);
    cudaGetSymbolAddress((void**)&p_wl, g_wt_l);
    cudaGetSymbolAddress((void**)&p_hh, g_hh);
    cudaGetSymbolAddress((void**)&p_hl, g_hl);
    cudaGetSymbolAddress((void**)&p_ahh, g_ahh);
    cudaGetSymbolAddress((void**)&p_ahl, g_ahl);
    cudaGetSymbolAddress((void**)&p_ffh, g_ffh);
    cudaGetSymbolAddress((void**)&p_ffl, g_ffl);

    static const size_t SLIDE_SMEM = (2 * 128 * 64) * sizeof(float);
    cudaFuncSetAttribute(sliding_attn_kernel,
                         cudaFuncAttributeMaxDynamicSharedMemorySize,
                         (int)SLIDE_SMEM);
    cudaFuncSetAttribute(gemm_mma_kernel,
                         cudaFuncAttributeMaxDynamicSharedMemorySize, SM_TOT);
    cudaFuncSetAttribute(gemm_mma_proj5_kernel,
                         cudaFuncAttributeMaxDynamicSharedMemorySize, SM_TOT);

    // ---- weight transpose + split ----
    const size_t OFF_W1 = 6 * (size_t)WT_MAT;
    const size_t OFF_W2 = OFF_W1 + (size_t)DD * FFD;
    {
        dim3 blk(32, 8);
        for (int l = 0; l < LL; l++) {
            size_t lb = (size_t)l * WT_LAYER;
            const float* srcs[6] = {Wq, Wk, Wv, Wkg, Wvg, Wo};
            for (int mi = 0; mi < 6; mi++) {
                size_t o = lb + (size_t)mi * WT_MAT;
                wt_conv_kernel<<<dim3(DD / 32, DD / 32), blk>>>(
                    srcs[mi] + (size_t)l * DD * DD, p_wh + o, p_wl + o, DD, DD);
            }
            wt_conv_kernel<<<dim3(FFD / 32, DD / 32), blk>>>(
                W1 + (size_t)l * DD * FFD, p_wh + lb + OFF_W1, p_wl + lb + OFF_W1,
                DD, FFD);
            wt_conv_kernel<<<dim3(DD / 32, FFD / 32), blk>>>(
                W2 + (size_t)l * FFD * DD, p_wh + lb + OFF_W2, p_wl + lb + OFF_W2,
                FFD, DD);
        }
    }

    // embedding + LN (emits h fp32 + split)
    embed_kernel<<<NTOK, 256>>>(src, emb_tok, emb_pos, p_t);
    add_ln_kernel<<<NTOK, 256>>>(p_t, nullptr, emb_ln_s, emb_ln_b,
                                 p_h, p_hh, p_hl);

    const int ACT4_D = NTOK * DD / 4;

    for (int l = 0; l < LL; l++) {
        const size_t lb  = (size_t)l * WT_LAYER;
        const size_t bo_ = (size_t)l * DD;

        // batched projections (q scaled by 0.125 in seg 0)
        Proj5 p;
        const float* biases[5] = {bq + bo_, bk + bo_, bv + bo_, bkg + bo_, bvg + bo_};
        float* outs[5] = {p_q, p_k, p_v, p_kg, p_vg};
        for (int s = 0; s < 5; s++) {
            p.bh[s] = p_wh + lb + (size_t)s * WT_MAT;
            p.bl[s] = p_wl + lb + (size_t)s * WT_MAT;
            p.bias[s] = biases[s];
            p.c[s] = outs[s];
        }
        gemm_mma_proj5_kernel<<<dim3(30, NTOK / 128), 256, SM_TOT>>>(p_hh, p_hl, p);
        qg_kernel<<<dim3(BB, 6), 128>>>(p_h, Wqg + (size_t)l * DD * DD, bqg + bo_, p_qg);

        // attention
        sliding_attn_kernel<<<dim3(NC, HH, BB), 128, SLIDE_SMEM>>>(
            p_q, p_k, p_v, mask_src, p_a);
        global_attn_kernel<<<dim3(HH, BB), 256>>>(
            p_qg, p_kg, p_vg, mask_src, p_a);

        // split attention output, output proj + residual LN
        act_conv_kernel<<<(ACT4_D + 255) / 256, 256>>>(p_a, p_ahh, p_ahl, ACT4_D);
        gemm_mma_kernel<<<dim3(6, NTOK / 128), 256, SM_TOT>>>(
            p_ahh, p_ahl,
            p_wh + lb + 5 * (size_t)WT_MAT, p_wl + lb + 5 * (size_t)WT_MAT,
            bo + bo_, p_t, nullptr, nullptr, DD, DD, 0, 1.f);
        add_ln_kernel<<<NTOK, 256>>>(p_t, p_h, ln1_s + bo_, ln1_b + bo_,
                                     p_h, p_hh, p_hl);

        // FFN: FFN1 writes split bf16 directly (GELU applied), FFN2 reads it
        gemm_mma_kernel<<<dim3(FFD / 128, NTOK / 128), 256, SM_TOT>>>(
            p_hh, p_hl, p_wh + lb + OFF_W1, p_wl + lb + OFF_W1,
            b1 + (size_t)l * FFD, nullptr, p_ffh, p_ffl, FFD, DD, 1, 1.f);
        gemm_mma_kernel<<<dim3(6, NTOK / 128), 256, SM_TOT>>>(
            p_ffh, p_ffl, p_wh + lb + OFF_W2, p_wl + lb + OFF_W2,
            b2 + bo_, p_t, nullptr, nullptr, DD, FFD, 0, 1.f);
        add_ln_kernel<<<NTOK, 256>>>(p_t, p_h, ln2_s + bo_, ln2_b + bo_,
                                     p_h, p_hh, p_hl);
    }

    cls_kernel<<<1, 32>>>(p_h, Wcls, bcls, mask_src, out);
}

// round 17
// speedup vs baseline: 1.9706x; 1.0738x over previous
#include <cuda_runtime.h>
#include <cuda_bf16.h>
#include <math.h>
#include <stdint.h>

// Problem constants (fixed inputs)
#define BB 2
#define SS 2048
#define DD 768
#define HH 12
#define DH 64
#define WW 128
#define NC (SS / WW)      // 16
#define LL 4
#define FFD 3072
#define NTOK (BB * SS)    // 4096

// ---------------- scratch (device globals; no allocation allowed) ----------
__device__ float g_h [NTOK * DD];
__device__ float g_q [NTOK * DD];
__device__ float g_k [NTOK * DD];
__device__ float g_v [NTOK * DD];
__device__ float g_kg[NTOK * DD];
__device__ float g_vg[NTOK * DD];
__device__ float g_t [NTOK * DD];
__device__ float g_qg[BB * DD];

// split bf16 activations
__device__ __align__(16) __nv_bfloat16 g_hh [NTOK * DD];
__device__ __align__(16) __nv_bfloat16 g_hl [NTOK * DD];
__device__ __align__(16) __nv_bfloat16 g_ahh[NTOK * DD];
__device__ __align__(16) __nv_bfloat16 g_ahl[NTOK * DD];
__device__ __align__(16) __nv_bfloat16 g_ffh[NTOK * FFD];
__device__ __align__(16) __nv_bfloat16 g_ffl[NTOK * FFD];

// transposed/split bf16 weights: per layer 6x(768x768) + w1(3072x768) + w2(768x3072)
#define WT_MAT   (DD * DD)
#define WT_LAYER (6 * WT_MAT + 2 * DD * FFD)
__device__ __align__(16) __nv_bfloat16 g_wt_h[LL * WT_LAYER];
__device__ __align__(16) __nv_bfloat16 g_wt_l[LL * WT_LAYER];

// ================= helpers ==================================================
__device__ __forceinline__ uint32_t smem_u32(const void* p) {
    uint32_t a;
    asm("{ .reg .u64 t; cvta.to.shared.u64 t, %1; cvt.u32.u64 %0, t; }"
        : "=r"(a) : "l"(p));
    return a;
}
__device__ __forceinline__ void ldsm_x4(uint32_t* r, uint32_t addr) {
    asm volatile("ldmatrix.sync.aligned.m8n8.x4.shared.b16 {%0,%1,%2,%3}, [%4];"
                 : "=r"(r[0]), "=r"(r[1]), "=r"(r[2]), "=r"(r[3]) : "r"(addr));
}
__device__ __forceinline__ void mma16816(float* d, const uint32_t* a,
                                         const uint32_t* b) {
    asm volatile("mma.sync.aligned.m16n8k16.row.col.f32.bf16.bf16.f32 "
                 "{%0,%1,%2,%3}, {%4,%5,%6,%7}, {%8,%9}, {%0,%1,%2,%3};"
                 : "+f"(d[0]), "+f"(d[1]), "+f"(d[2]), "+f"(d[3])
                 : "r"(a[0]), "r"(a[1]), "r"(a[2]), "r"(a[3]),
                   "r"(b[0]), "r"(b[1]));
}
#define CP_ASYNC16(dst, src) \
    asm volatile("cp.async.cg.shared.global [%0], [%1], 16;" \
                 :: "r"(dst), "l"(src))
#define CP_COMMIT() asm volatile("cp.async.commit_group;" ::: "memory")
#define CP_WAIT1()  asm volatile("cp.async.wait_group 1;" ::: "memory")
#define CP_WAIT0()  asm volatile("cp.async.wait_group 0;" ::: "memory")

// ================= mma.sync GEMM (cp.async double-buffered) =================
// C = (A @ W + bias) * scale (+gelu).  A pre-split Ah/Al [M,K] bf16;
// W pre-transposed+split Bh/Bl [N,K] bf16.  CTA tile 128x64 (2+ CTAs/SM),
// 8 warps (4m x 2n), warp tile 32x32, K-chunk 32.  3 terms:
// ah*bh + al*bh + ah*bl.  80B smem row pitch -> conflict-free ldmatrix.
// Output: fp32 C, or split bf16 (Ch,Cl) when Cl != nullptr.
#define SM_AH 0
#define SM_AL 10240
#define SM_BH 20480
#define SM_BL 25600
#define SM_BUF 30720
#define SM_TOT (2 * SM_BUF)   // 61440 dynamic

__device__ __forceinline__ void gemm_mma_core(
    const __nv_bfloat16* __restrict__ Ah, const __nv_bfloat16* __restrict__ Al,
    const __nv_bfloat16* __restrict__ Bh, const __nv_bfloat16* __restrict__ Bl,
    const float* __restrict__ bias, float* __restrict__ C,
    __nv_bfloat16* __restrict__ Ch, __nv_bfloat16* __restrict__ Cl,
    int N, int K, int ep, float scale, int brow, int bcol, char* sm)
{
    const uint32_t smb = smem_u32(sm);
    const int tid  = threadIdx.x;
    const int lane = tid & 31, wrp = tid >> 5;
    const int wm = wrp >> 1, wn = wrp & 1;       // 4x2 warp grid

    float acc[2][4][4];
#pragma unroll
    for (int mt = 0; mt < 2; mt++)
#pragma unroll
        for (int nt = 0; nt < 4; nt++)
#pragma unroll
            for (int j = 0; j < 4; j++) acc[mt][nt][j] = 0.f;

    const int nch = K >> 5;

    // ---- async stage of one 32-k chunk into buffer bb ----------------------
    auto load_chunk = [&](int ch, int bb) {
        const int k0 = ch << 5;
        const uint32_t base = smb + bb * SM_BUF;
#pragma unroll
        for (int i = 0; i < 2; i++) {                 // A: 128 rows x 4 segs
            int idx = tid + i * 256;
            int row = idx >> 2, seg = idx & 3;
            uint32_t off = row * 80 + seg * 16;
            size_t ga = (size_t)(brow + row) * K + k0 + seg * 8;
            CP_ASYNC16(base + SM_AH + off, &Ah[ga]);
            CP_ASYNC16(base + SM_AL + off, &Al[ga]);
        }
        {                                             // B: 64 rows x 4 segs
            int row = tid >> 2, seg = tid & 3;
            uint32_t off = row * 80 + seg * 16;
            size_t gb = (size_t)(bcol + row) * K + k0 + seg * 8;
            CP_ASYNC16(base + SM_BH + off, &Bh[gb]);
            CP_ASYNC16(base + SM_BL + off, &Bl[gb]);
        }
        CP_COMMIT();
    };

    load_chunk(0, 0);
    for (int ch = 0; ch < nch; ch++) {
        if (ch + 1 < nch) { load_chunk(ch + 1, (ch + 1) & 1); CP_WAIT1(); }
        else              { CP_WAIT0(); }
        __syncthreads();
        const uint32_t base = smb + (ch & 1) * SM_BUF;

#pragma unroll
        for (int ks = 0; ks < 2; ks++) {
            const uint32_t kb = ks * 32 + ((lane >> 3) & 1) * 16;  // B k-byte
            const uint32_t ka = ks * 32 + (lane >> 4) * 16;        // A k-byte
            uint32_t ah[2][4], aw[2][4], bb[4][2];
            // A-hi fragments
#pragma unroll
            for (int mt = 0; mt < 2; mt++) {
                uint32_t r = wm * 32 + mt * 16 + (lane & 15);
                ldsm_x4(ah[mt], base + SM_AH + r * 80 + ka);
            }
            // B-hi fragments (pairs of n8 tiles)
#pragma unroll
            for (int p = 0; p < 2; p++) {
                uint32_t r = wn * 32 + p * 16 + ((lane >> 4) & 1) * 8 + (lane & 7);
                uint32_t t4[4];
                ldsm_x4(t4, base + SM_BH + r * 80 + kb);
                bb[2 * p][0] = t4[0]; bb[2 * p][1] = t4[1];
                bb[2 * p + 1][0] = t4[2]; bb[2 * p + 1][1] = t4[3];
            }
            // term 1: ah * bh
#pragma unroll
            for (int mt = 0; mt < 2; mt++)
#pragma unroll
                for (int nt = 0; nt < 4; nt++)
                    mma16816(acc[mt][nt], ah[mt], bb[nt]);
            // A-lo fragments; term 2: al * bh
#pragma unroll
            for (int mt = 0; mt < 2; mt++) {
                uint32_t r = wm * 32 + mt * 16 + (lane & 15);
                ldsm_x4(aw[mt], base + SM_AL + r * 80 + ka);
            }
#pragma unroll
            for (int mt = 0; mt < 2; mt++)
#pragma unroll
                for (int nt = 0; nt < 4; nt++)
                    mma16816(acc[mt][nt], aw[mt], bb[nt]);
            // B-lo fragments (reuse bb); term 3: ah * bl
#pragma unroll
            for (int p = 0; p < 2; p++) {
                uint32_t r = wn * 32 + p * 16 + ((lane >> 4) & 1) * 8 + (lane & 7);
                uint32_t t4[4];
                ldsm_x4(t4, base + SM_BL + r * 80 + kb);
                bb[2 * p][0] = t4[0]; bb[2 * p][1] = t4[1];
                bb[2 * p + 1][0] = t4[2]; bb[2 * p + 1][1] = t4[3];
            }
#pragma unroll
            for (int mt = 0; mt < 2; mt++)
#pragma unroll
                for (int nt = 0; nt < 4; nt++)
                    mma16816(acc[mt][nt], ah[mt], bb[nt]);
        }
        __syncthreads();
    }

    // ---- epilogue: direct stores (c-frag layout) ---------------------------
#pragma unroll
    for (int mt = 0; mt < 2; mt++) {
        int row0 = brow + wm * 32 + mt * 16 + (lane >> 2);
#pragma unroll
        for (int nt = 0; nt < 4; nt++) {
            int col = bcol + wn * 32 + nt * 8 + (lane & 3) * 2;
            float b0 = bias[col], b1 = bias[col + 1];
#pragma unroll
            for (int h = 0; h < 2; h++) {
                int r = row0 + h * 8;
                float v0 = (acc[mt][nt][2 * h + 0] + b0) * scale;
                float v1 = (acc[mt][nt][2 * h + 1] + b1) * scale;
                if (ep) {
                    v0 = 0.5f * v0 * (1.f + erff(v0 * 0.70710678118654752f));
                    v1 = 0.5f * v1 * (1.f + erff(v1 * 0.70710678118654752f));
                }
                if (Cl) {
                    __nv_bfloat16 h0 = __float2bfloat16_rn(v0);
                    __nv_bfloat16 h1 = __float2bfloat16_rn(v1);
                    __nv_bfloat162 hp; hp.x = h0; hp.y = h1;
                    *(__nv_bfloat162*)&Ch[(size_t)r * N + col] = hp;
                    __nv_bfloat162 lp;
                    lp.x = __float2bfloat16_rn(v0 - __bfloat162float(h0));
                    lp.y = __float2bfloat16_rn(v1 - __bfloat162float(h1));
                    *(__nv_bfloat162*)&Cl[(size_t)r * N + col] = lp;
                } else {
                    *(float2*)&C[(size_t)r * N + col] = make_float2(v0, v1);
                }
            }
        }
    }
}

__global__ __launch_bounds__(256, 2) void gemm_mma_kernel(
    const __nv_bfloat16* __restrict__ Ah, const __nv_bfloat16* __restrict__ Al,
    const __nv_bfloat16* __restrict__ Bh, const __nv_bfloat16* __restrict__ Bl,
    const float* __restrict__ bias, float* __restrict__ C,
    __nv_bfloat16* Ch, __nv_bfloat16* Cl,
    int N, int K, int ep, float scale)
{
    extern __shared__ char sm[];
    gemm_mma_core(Ah, Al, Bh, Bl, bias, C, Ch, Cl, N, K, ep, scale,
                  blockIdx.y * 128, blockIdx.x * 64, sm);
}

// batched 5-projection GEMM (q,k,v,kg,vg) sharing A; N=768 each, K=768.
struct Proj5 {
    const __nv_bfloat16* bh[5];
    const __nv_bfloat16* bl[5];
    const float* bias[5];
    float* c[5];
};
__global__ __launch_bounds__(256, 2) void gemm_mma_proj5_kernel(
    const __nv_bfloat16* __restrict__ Ah, const __nv_bfloat16* __restrict__ Al,
    Proj5 p)
{
    extern __shared__ char sm[];
    const int seg  = blockIdx.x / 12;
    const int bcol = (blockIdx.x % 12) * 64;
    const float scale = (seg == 0) ? 0.125f : 1.f;
    gemm_mma_core(Ah, Al, p.bh[seg], p.bl[seg], p.bias[seg], p.c[seg],
                  nullptr, nullptr, DD, DD, 0, scale,
                  blockIdx.y * 128, bcol, sm);
}

// ---------------- weight transpose + hi/lo split -----------------------------
// batched: 6 square mats x 4 layers in one launch (grid.z = 24)
struct Wt6 { const float* s[6]; };
__global__ __launch_bounds__(256) void wt_conv6_kernel(
    Wt6 job, __nv_bfloat16* __restrict__ oh, __nv_bfloat16* __restrict__ ol)
{
    __shared__ float ts[32][33];
    int l = blockIdx.z / 6, mi = blockIdx.z % 6;
    const float* W = job.s[mi] + (size_t)l * DD * DD;
    size_t dst = (size_t)l * WT_LAYER + (size_t)mi * WT_MAT;
    int nb = blockIdx.x * 32, kb = blockIdx.y * 32;
    int tx = threadIdx.x, ty = threadIdx.y;
#pragma unroll
    for (int i = ty; i < 32; i += 8)
        ts[i][tx] = W[(size_t)(kb + i) * DD + nb + tx];
    __syncthreads();
#pragma unroll
    for (int i = ty; i < 32; i += 8) {
        float x = ts[tx][i];
        __nv_bfloat16 h = __float2bfloat16_rn(x);
        size_t o = dst + (size_t)(nb + i) * DD + kb + tx;
        oh[o] = h;
        ol[o] = __float2bfloat16_rn(x - __bfloat162float(h));
    }
}
// ffn weights: grid.z = 4 layers
__global__ __launch_bounds__(256) void wt_conv_ff_kernel(
    const float* __restrict__ Wsrc, __nv_bfloat16* __restrict__ oh,
    __nv_bfloat16* __restrict__ ol, int K, int N, size_t dst_off)
{
    __shared__ float ts[32][33];
    int l = blockIdx.z;
    const float* W = Wsrc + (size_t)l * K * N;
    size_t dst = (size_t)l * WT_LAYER + dst_off;
    int nb = blockIdx.x * 32, kb = blockIdx.y * 32;
    int tx = threadIdx.x, ty = threadIdx.y;
#pragma unroll
    for (int i = ty; i < 32; i += 8)
        ts[i][tx] = W[(size_t)(kb + i) * N + nb + tx];
    __syncthreads();
#pragma unroll
    for (int i = ty; i < 32; i += 8) {
        float x = ts[tx][i];
        __nv_bfloat16 h = __float2bfloat16_rn(x);
        size_t o = dst + (size_t)(nb + i) * K + kb + tx;
        oh[o] = h;
        ol[o] = __float2bfloat16_rn(x - __bfloat162float(h));
    }
}

// ---------------- embedding gather ------------------------------------------
__global__ void embed_kernel(const int* __restrict__ src,
                             const float* __restrict__ tok,
                             const float* __restrict__ pos,
                             float* __restrict__ out)
{
    int row = blockIdx.x;
    int s = row % SS;
    int t = src[row];
    for (int i = threadIdx.x; i < DD; i += blockDim.x)
        out[(size_t)row * DD + i] = tok[(size_t)t * DD + i] + pos[(size_t)s * DD + i];
}

// ---------------- add + layernorm (emits fp32 + split bf16) ------------------
__global__ __launch_bounds__(256) void add_ln_kernel(
    const float* __restrict__ x, const float* __restrict__ res,
    const float* __restrict__ gam, const float* __restrict__ bet,
    float* __restrict__ out,
    __nv_bfloat16* __restrict__ oh, __nv_bfloat16* __restrict__ ol)
{
    int row = blockIdx.x;
    int tid = threadIdx.x;
    const float* xr = x + (size_t)row * DD;
    const float* rr = res ? res + (size_t)row * DD : nullptr;
    float v[3];
    float lsum = 0.f, lsq = 0.f;
#pragma unroll
    for (int i = 0; i < 3; i++) {
        int idx = tid + i * 256;
        float t = xr[idx];
        if (rr) t += rr[idx];
        v[i] = t; lsum += t; lsq += t * t;
    }
    __shared__ float r1[256], r2[256];
    r1[tid] = lsum; r2[tid] = lsq;
    __syncthreads();
    for (int o = 128; o > 0; o >>= 1) {
        if (tid < o) { r1[tid] += r1[tid + o]; r2[tid] += r2[tid + o]; }
        __syncthreads();
    }
    float mean = r1[0] * (1.f / DD);
    float var  = r2[0] * (1.f / DD) - mean * mean;
    float inv  = rsqrtf(var + 1e-5f);
#pragma unroll
    for (int i = 0; i < 3; i++) {
        int idx = tid + i * 256;
        size_t o = (size_t)row * DD + idx;
        float vv = (v[i] - mean) * inv * gam[idx] + bet[idx];
        out[o] = vv;
        __nv_bfloat16 hb = __float2bfloat16_rn(vv);
        oh[o] = hb;
        ol[o] = __float2bfloat16_rn(vv - __bfloat162float(hb));
    }
}

// ---------------- qg = (h[:,0] @ Wqg + bqg) / 8 ------------------------------
__global__ __launch_bounds__(128) void qg_kernel(
    const float* __restrict__ h, const float* __restrict__ W,
    const float* __restrict__ b, float* __restrict__ qg)
{
    __shared__ float hs[DD];
    int bb = blockIdx.x;
    for (int i = threadIdx.x; i < DD; i += 128)
        hs[i] = h[(size_t)bb * SS * DD + i];
    __syncthreads();
    int n = blockIdx.y * 128 + threadIdx.x;
    float acc = b[n];
#pragma unroll 4
    for (int k = 0; k < DD; k++) acc += hs[k] * W[(size_t)k * DD + n];
    qg[bb * DD + n] = acc * 0.125f;
}

// ---------------- sliding-window + global-slot attention ---------------------
// writes split bf16 output directly
__global__ __launch_bounds__(128) void sliding_attn_kernel(
    const float* __restrict__ q, const float* __restrict__ k,
    const float* __restrict__ v, const int* __restrict__ mask,
    __nv_bfloat16* __restrict__ oh, __nv_bfloat16* __restrict__ ol)
{
    extern __shared__ float smd[];
    float* ks = smd;
    float* vs = smd + 128 * 64;

    const int c = blockIdx.x, hh = blockIdx.y, b = blockIdx.z;
    const int qi = threadIdx.x;
    const int t  = c * WW + qi;
    const size_t base = (size_t)(b * SS) * DD + hh * DH;

    float qr[DH];
#pragma unroll
    for (int d = 0; d < DH; d++)
        qr[d] = q[base + (size_t)t * DD + d];

    float m, l, acc[DH];
    {
        float sc;
        if (mask[b * SS + 0] != 0) {
            sc = 0.f;
#pragma unroll
            for (int d = 0; d < DH; d++)
                sc += qr[d] * k[base + d];
        } else sc = -1e9f;
        m = sc; l = 1.f;
#pragma unroll
        for (int d = 0; d < DH; d++) acc[d] = v[base + d];
    }

    for (int tile = 0; tile < 3; tile++) {
        int s0 = c * WW - WW + tile * WW;
        __syncthreads();
        for (int li = qi; li < 128 * 64; li += 128) {
            int j = li >> 6, d = li & 63;
            int srow = s0 + j;
            float kv = 0.f, vv = 0.f;
            if (srow >= 0 && srow < SS) {
                kv = k[base + (size_t)srow * DD + d];
                vv = v[base + (size_t)srow * DD + d];
            }
            ks[j * 64 + d] = kv;
            vs[j * 64 + d] = vv;
        }
        __syncthreads();

        for (int j = 0; j < 128; j++) {
            int jj = tile * 128 + j;
            if (jj < qi || jj > qi + 2 * WW) continue;
            int srow = s0 + j;
            if (srow < 0 || srow >= SS) continue;
            if (mask[b * SS + srow] == 0) continue;
            float sc = 0.f;
#pragma unroll
            for (int d = 0; d < DH; d++)
                sc += qr[d] * ks[j * 64 + d];
            if (sc > m) {
                float f = expf(m - sc);
                l *= f;
#pragma unroll
                for (int d = 0; d < DH; d++) acc[d] *= f;
                m = sc;
            }
            float w = expf(sc - m);
            l += w;
#pragma unroll
            for (int d = 0; d < DH; d++) acc[d] += w * vs[j * 64 + d];
        }
    }

    float invl = 1.f / l;
#pragma unroll
    for (int d = 0; d < DH; d++) {
        float vv = acc[d] * invl;
        size_t o = base + (size_t)t * DD + d;
        __nv_bfloat16 hb = __float2bfloat16_rn(vv);
        oh[o] = hb;
        ol[o] = __float2bfloat16_rn(vv - __bfloat162float(hb));
    }
}

// ---------------- global attention for token 0 (writes split bf16) -----------
__global__ __launch_bounds__(256) void global_attn_kernel(
    const float* __restrict__ qg, const float* __restrict__ kg,
    const float* __restrict__ vg, const int* __restrict__ mask,
    __nv_bfloat16* __restrict__ oh, __nv_bfloat16* __restrict__ ol)
{
    __shared__ float sc[SS];
    __shared__ float red[256];
    const int hh = blockIdx.x, b = blockIdx.y;
    const int tid = threadIdx.x;
    const size_t base = (size_t)(b * SS) * DD + hh * DH;

    float qr[DH];
#pragma unroll
    for (int d = 0; d < DH; d++) qr[d] = qg[b * DD + hh * DH + d];

    for (int s = tid; s < SS; s += 256) {
        float d0;
        if (mask[b * SS + s] != 0) {
            d0 = 0.f;
#pragma unroll
            for (int d = 0; d < DH; d++)
                d0 += qr[d] * kg[base + (size_t)s * DD + d];
        } else d0 = -1e9f;
        sc[s] = d0;
    }
    __syncthreads();

    float mx = -1e30f;
    for (int s = tid; s < SS; s += 256) mx = fmaxf(mx, sc[s]);
    red[tid] = mx; __syncthreads();
    for (int o = 128; o > 0; o >>= 1) {
        if (tid < o) red[tid] = fmaxf(red[tid], red[tid + o]);
        __syncthreads();
    }
    mx = red[0];
    __syncthreads();

    float ps = 0.f;
    for (int s = tid; s < SS; s += 256) {
        float e = expf(sc[s] - mx);
        sc[s] = e; ps += e;
    }
    red[tid] = ps; __syncthreads();
    for (int o = 128; o > 0; o >>= 1) {
        if (tid < o) red[tid] += red[tid + o];
        __syncthreads();
    }
    float total = red[0];
    __syncthreads();

    int d = tid & 63, g = tid >> 6;
    float a = 0.f;
    for (int s = g; s < SS; s += 4)
        a += sc[s] * vg[base + (size_t)s * DD + d];
    red[tid] = a; __syncthreads();
    if (g == 0) {
        a = red[tid] + red[tid + 64] + red[tid + 128] + red[tid + 192];
        float vv = a / total;
        __nv_bfloat16 hb = __float2bfloat16_rn(vv);
        oh[base + d] = hb;
        ol[base + d] = __float2bfloat16_rn(vv - __bfloat162float(hb));
    }
}

// ---------------- classifier head -------------------------------------------
__global__ void cls_kernel(const float* __restrict__ h,
                           const float* __restrict__ Wc,
                           const float* __restrict__ bc,
                           const int* __restrict__ mask,
                           float* __restrict__ out)
{
    int tid = threadIdx.x;
    if (tid < BB * 3) {
        int b = tid / 3, j = tid % 3;
        const float* hr = h + (size_t)b * SS * DD;
        float acc = bc[j];
        for (int kx = 0; kx < DD; kx++) acc += hr[kx] * Wc[kx * 3 + j];
        float sg = 1.f / (1.f + expf(-acc));
        out[j * BB + b] = sg;
        if (j == 0) out[3 * BB + b] = (float)mask[b * SS + 0];
    }
}

// ---------------- host orchestration -----------------------------------------
extern "C" void kernel_launch(void* const* d_in, const int* in_sizes, int n_in,
                              void* d_out, int out_size)
{
    const int*   src      = (const int*)  d_in[0];
    const int*   mask_src = (const int*)  d_in[1];
    const float* emb_tok  = (const float*)d_in[3];
    const float* emb_pos  = (const float*)d_in[4];
    const float* emb_ln_s = (const float*)d_in[5];
    const float* emb_ln_b = (const float*)d_in[6];
    const float* Wq  = (const float*)d_in[7];
    const float* bq  = (const float*)d_in[8];
    const float* Wk  = (const float*)d_in[9];
    const float* bk  = (const float*)d_in[10];
    const float* Wv  = (const float*)d_in[11];
    const float* bv  = (const float*)d_in[12];
    const float* Wo  = (const float*)d_in[13];
    const float* bo  = (const float*)d_in[14];
    const float* Wqg = (const float*)d_in[15];
    const float* bqg = (const float*)d_in[16];
    const float* Wkg = (const float*)d_in[17];
    const float* bkg = (const float*)d_in[18];
    const float* Wvg = (const float*)d_in[19];
    const float* bvg = (const float*)d_in[20];
    const float* ln1_s = (const float*)d_in[21];
    const float* ln1_b = (const float*)d_in[22];
    const float* W1  = (const float*)d_in[23];
    const float* b1  = (const float*)d_in[24];
    const float* W2  = (const float*)d_in[25];
    const float* b2  = (const float*)d_in[26];
    const float* ln2_s = (const float*)d_in[27];
    const float* ln2_b = (const float*)d_in[28];
    const float* Wcls = (const float*)d_in[29];
    const float* bcls = (const float*)d_in[30];
    float* out = (float*)d_out;

    float *p_h, *p_q, *p_k, *p_v, *p_kg, *p_vg, *p_t, *p_qg;
    __nv_bfloat16 *p_wh, *p_wl, *p_hh, *p_hl, *p_ahh, *p_ahl, *p_ffh, *p_ffl;
    cudaGetSymbolAddress((void**)&p_h,  g_h);
    cudaGetSymbolAddress((void**)&p_q,  g_q);
    cudaGetSymbolAddress((void**)&p_k,  g_k);
    cudaGetSymbolAddress((void**)&p_v,  g_v);
    cudaGetSymbolAddress((void**)&p_kg, g_kg);
    cudaGetSymbolAddress((void**)&p_vg, g_vg);
    cudaGetSymbolAddress((void**)&p_t,  g_t);
    cudaGetSymbolAddress((void**)&p_qg, g_qg);
    cudaGetSymbolAddress((void**)&p_wh, g_wt_h);
    cudaGetSymbolAddress((void**)&p_wl, g_wt_l);
    cudaGetSymbolAddress((void**)&p_hh, g_hh);
    cudaGetSymbolAddress((void**)&p_hl, g_hl);
    cudaGetSymbolAddress((void**)&p_ahh, g_ahh);
    cudaGetSymbolAddress((void**)&p_ahl, g_ahl);
    cudaGetSymbolAddress((void**)&p_ffh, g_ffh);
    cudaGetSymbolAddress((void**)&p_ffl, g_ffl);

    static const size_t SLIDE_SMEM = (2 * 128 * 64) * sizeof(float);
    cudaFuncSetAttribute(sliding_attn_kernel,
                         cudaFuncAttributeMaxDynamicSharedMemorySize,
                         (int)SLIDE_SMEM);
    cudaFuncSetAttribute(gemm_mma_kernel,
                         cudaFuncAttributeMaxDynamicSharedMemorySize, SM_TOT);
    cudaFuncSetAttribute(gemm_mma_proj5_kernel,
                         cudaFuncAttributeMaxDynamicSharedMemorySize, SM_TOT);

    // ---- weight transpose + split (3 launches) ----
    const size_t OFF_W1 = 6 * (size_t)WT_MAT;
    const size_t OFF_W2 = OFF_W1 + (size_t)DD * FFD;
    {
        dim3 blk(32, 8);
        Wt6 job;
        job.s[0] = Wq; job.s[1] = Wk; job.s[2] = Wv;
        job.s[3] = Wkg; job.s[4] = Wvg; job.s[5] = Wo;
        wt_conv6_kernel<<<dim3(DD / 32, DD / 32, 6 * LL), blk>>>(job, p_wh, p_wl);
        wt_conv_ff_kernel<<<dim3(FFD / 32, DD / 32, LL), blk>>>(
            W1, p_wh, p_wl, DD, FFD, OFF_W1);
        wt_conv_ff_kernel<<<dim3(DD / 32, FFD / 32, LL), blk>>>(
            W2, p_wh, p_wl, FFD, DD, OFF_W2);
    }

    // embedding + LN (emits h fp32 + split)
    embed_kernel<<<NTOK, 256>>>(src, emb_tok, emb_pos, p_t);
    add_ln_kernel<<<NTOK, 256>>>(p_t, nullptr, emb_ln_s, emb_ln_b,
                                 p_h, p_hh, p_hl);

    for (int l = 0; l < LL; l++) {
        const size_t lb  = (size_t)l * WT_LAYER;
        const size_t bo_ = (size_t)l * DD;

        // batched projections (q scaled by 0.125 in seg 0)
        Proj5 p;
        const float* biases[5] = {bq + bo_, bk + bo_, bv + bo_, bkg + bo_, bvg + bo_};
        float* outs[5] = {p_q, p_k, p_v, p_kg, p_vg};
        for (int s = 0; s < 5; s++) {
            p.bh[s] = p_wh + lb + (size_t)s * WT_MAT;
            p.bl[s] = p_wl + lb + (size_t)s * WT_MAT;
            p.bias[s] = biases[s];
            p.c[s] = outs[s];
        }
        gemm_mma_proj5_kernel<<<dim3(60, NTOK / 128), 256, SM_TOT>>>(p_hh, p_hl, p);
        qg_kernel<<<dim3(BB, 6), 128>>>(p_h, Wqg + (size_t)l * DD * DD, bqg + bo_, p_qg);

        // attention (writes split bf16 output directly)
        sliding_attn_kernel<<<dim3(NC, HH, BB), 128, SLIDE_SMEM>>>(
            p_q, p_k, p_v, mask_src, p_ahh, p_ahl);
        global_attn_kernel<<<dim3(HH, BB), 256>>>(
            p_qg, p_kg, p_vg, mask_src, p_ahh, p_ahl);

        // output proj + residual LN
        gemm_mma_kernel<<<dim3(12, NTOK / 128), 256, SM_TOT>>>(
            p_ahh, p_ahl,
            p_wh + lb + 5 * (size_t)WT_MAT, p_wl + lb + 5 * (size_t)WT_MAT,
            bo + bo_, p_t, nullptr, nullptr, DD, DD, 0, 1.f);
        add_ln_kernel<<<NTOK, 256>>>(p_t, p_h, ln1_s + bo_, ln1_b + bo_,
                                     p_h, p_hh, p_hl);

        // FFN: FFN1 writes split bf16 directly (GELU applied), FFN2 reads it
        gemm_mma_kernel<<<dim3(FFD / 64, NTOK / 128), 256, SM_TOT>>>(
            p_hh, p_hl, p_wh + lb + OFF_W1, p_wl + lb + OFF_W1,
            b1 + (size_t)l * FFD, nullptr, p_ffh, p_ffl, FFD, DD, 1, 1.f);
        gemm_mma_kernel<<<dim3(12, NTOK / 128), 256, SM_TOT>>>(
            p_ffh, p_ffl, p_wh + lb + OFF_W2, p_wl + lb + OFF_W2,
            b2 + bo_, p_t, nullptr, nullptr, DD, FFD, 0, 1.f);
        add_ln_kernel<<<NTOK, 256>>>(p_t, p_h, ln2_s + bo_, ln2_b + bo_,
                                     p_h, p_hh, p_hl);
    }

    cls_kernel<<<1, 32>>>(p_h, Wcls, bcls, mask_src, out);
}